// round 14
// baseline (speedup 1.0000x reference)
#include <cuda_runtime.h>
#include <cstdint>

#define NN 200000
#define NE 800000
#define NG 4096
#define KDRUG 78
#define KPAD 80
#define KCELL 954
#define HF 128
#define BN_EPS 1e-5f
#define SCAN_NB 98   // ceil(NN/2048)

// ---------------- scratch (zero-init at load; every run restores zeros) ----------------
__device__ int   g_cnt[NN];
__device__ int   g_fill[NN];
__device__ int   g_off[NN + 1];
__device__ int   g_bsum[SCAN_NB];
__device__ int   g_csr[NE];
__device__ float g_dinv[NN];
__device__ float g_t[NN];
__device__ float g_dp[(size_t)NN * KPAD];
__device__ float g_h[(size_t)NN * KPAD];    // agg1 [NN,80] (tf32-rounded)
__device__ float g_y[(size_t)NN * HF];      // agg2 [NN,128] (tf32-rounded)
__device__ float g_x[(size_t)NN * HF];      // relu(out1) (tf32-rounded)
__device__ float g_W1p[KPAD * HF];          // W1 padded [80][128] (tf32-rounded)
__device__ float g_W2p[HF * HF];            // folded W2 [k][n] (tf32-rounded)
__device__ float g_stat1[2 * HF];
__device__ float g_stat2[2 * HF];
__device__ float g_statc[2 * HF];
__device__ float g_c2[HF];
__device__ float g_Wc2p[HF * HF];
__device__ float g_bc2p[HF];
__device__ float g_smax[NG * HF];
__device__ float g_smin[NG * HF];
__device__ float g_cell[(size_t)NG * HF];

__device__ __forceinline__ float neg_inf() { return __int_as_float(0xff800000); }
__device__ __forceinline__ float pos_inf() { return __int_as_float(0x7f800000); }
__device__ __forceinline__ float f2tf(float f) {
    uint32_t u;
    asm("cvt.rna.tf32.f32 %0, %1;" : "=r"(u) : "f"(f));
    return __uint_as_float(u);
}

#define CP_A16(saddr, gptr, ssz) \
    asm volatile("cp.async.ca.shared.global [%0], [%1], 16, %2;" :: "r"(saddr), "l"(gptr), "r"(ssz))
#define CP_COMMIT() asm volatile("cp.async.commit_group;" ::: "memory")

// ---------------- tiny no-op kernel (capture fork anchor) ----------------
__global__ void k_nop() {}

// ---------------- edge count (g_cnt arrives zeroed) ----------------
__global__ void k_cnt(const int* __restrict__ ei) {
    int e = blockIdx.x * blockDim.x + threadIdx.x;
    if (e < NE) atomicAdd(&g_cnt[ei[NE + e]], 1);
}

// ---------------- dinv from indegree ----------------
__global__ void k_dinv() {
    int i = blockIdx.x * blockDim.x + threadIdx.x;
    if (i < NN) g_dinv[i] = rsqrtf((float)(1 + g_cnt[i]));
}

// ---------------- init pool accumulators (-inf / +inf) + zero stat2 ----------------
__global__ void k_ginit() {
    int idx = blockIdx.x * blockDim.x + threadIdx.x;
    if (idx < 2 * HF) g_stat2[idx] = 0.f;   // gemm2 is ordered after this via eGB
    if (idx < NG * HF) { g_smax[idx] = neg_inf(); g_smin[idx] = pos_inf(); }
}

// ---------------- CSR scan ----------------
__global__ void __launch_bounds__(256) k_scan1() {
    __shared__ int wsum[8];
    __shared__ int woff[8];
    int t = threadIdx.x;
    int base = blockIdx.x * 2048 + t * 8;
    int v[8];
    int run = 0;
#pragma unroll
    for (int j = 0; j < 8; j++) {
        int idx = base + j;
        int c = (idx < NN) ? g_cnt[idx] : 0;
        v[j] = run;
        run += c;
    }
    int lane = t & 31, w = t >> 5;
    int x = run;
#pragma unroll
    for (int o = 1; o < 32; o <<= 1) {
        int y = __shfl_up_sync(0xffffffffu, x, o);
        if (lane >= o) x += y;
    }
    if (lane == 31) wsum[w] = x;
    __syncthreads();
    if (t == 0) {
        int r = 0;
#pragma unroll
        for (int k = 0; k < 8; k++) { woff[k] = r; r += wsum[k]; }
        g_bsum[blockIdx.x] = r;
    }
    __syncthreads();
    int texc = x - run + woff[w];
#pragma unroll
    for (int j = 0; j < 8; j++) {
        int idx = base + j;
        if (idx < NN) g_off[idx] = texc + v[j];
    }
}

__global__ void __launch_bounds__(256) k_scan3() {
    __shared__ int raw[SCAN_NB];
    __shared__ int pref[SCAN_NB];
    int t = threadIdx.x;
    if (t < SCAN_NB) raw[t] = g_bsum[t];
    __syncthreads();
    if (t == 0) {
        int r = 0;
#pragma unroll 7
        for (int b = 0; b < SCAN_NB; b++) { pref[b] = r; r += raw[b]; }
    }
    __syncthreads();
    int i = blockIdx.x * blockDim.x + t;
    if (i < NN) g_off[i] += pref[i >> 11];
    if (i == 0) g_off[NN] = NE;
}

__global__ void k_fill(const int* __restrict__ ei) {
    int e = blockIdx.x * blockDim.x + threadIdx.x;
    if (e < NE) {
        int d = ei[NE + e];
        int pos = g_off[d] + atomicAdd(&g_fill[d], 1);
        g_csr[pos] = ei[e];
    }
}

// ---------------- pad W1 [78,128] -> [80,128], tf32-rounded ----------------
__global__ void k_padW(const float* __restrict__ W1) {
    int idx = blockIdx.x * blockDim.x + threadIdx.x;
    if (idx >= KPAD * HF) return;
    int row = idx >> 7;
    g_W1p[idx] = (row < KDRUG) ? f2tf(W1[idx]) : 0.f;
}

// ---------------- pad drug [NN,78]->[NN,80] (no deps; runs at t=0) ----------------
__global__ void k_padDrug(const float* __restrict__ drug) {
    int idx = blockIdx.x * blockDim.x + threadIdx.x;
    if (idx >= NN * 40) return;
    int i = idx / 40, s = idx - i * 40;
    float2 v = make_float2(0.f, 0.f);
    if (s < 39) v = ((const float2*)drug)[(size_t)i * 39 + s];
    ((float2*)g_dp)[idx] = v;
}

// ---------------- CSR gather (tf32-rounded output), 4x unrolled ----------------
template <int NF4, bool WRITE_T, bool CLEAN>
__global__ void __launch_bounds__(256) k_gather(const float* __restrict__ src,
                                                float* __restrict__ dst) {
    int gw = (blockIdx.x * 256 + threadIdx.x) >> 5;
    if (gw >= NN) return;
    int lane = threadIdx.x & 31;
    if (CLEAN && lane == 0) { g_cnt[gw] = 0; g_fill[gw] = 0; }
    float di = g_dinv[gw];
    int beg = g_off[gw], end = g_off[gw + 1];
    const float4* S = (const float4*)src;
    float4 acc = make_float4(0.f, 0.f, 0.f, 0.f);
    if (lane < NF4) {
        float4 v = S[(size_t)gw * NF4 + lane];
        float a = di * di;
        acc = make_float4(v.x * a, v.y * a, v.z * a, v.w * a);
    }
    float tacc = di;
    int e = beg;
    for (; e + 3 < end; e += 4) {
        int s0 = g_csr[e], s1 = g_csr[e + 1], s2 = g_csr[e + 2], s3 = g_csr[e + 3];
        float d0 = g_dinv[s0], d1 = g_dinv[s1], d2 = g_dinv[s2], d3 = g_dinv[s3];
        tacc += (d0 + d1) + (d2 + d3);
        if (lane < NF4) {
            float4 v0 = S[(size_t)s0 * NF4 + lane];
            float4 v1 = S[(size_t)s1 * NF4 + lane];
            float4 v2 = S[(size_t)s2 * NF4 + lane];
            float4 v3 = S[(size_t)s3 * NF4 + lane];
            float w0 = di * d0, w1 = di * d1, w2 = di * d2, w3 = di * d3;
            acc.x += (w0 * v0.x + w1 * v1.x) + (w2 * v2.x + w3 * v3.x);
            acc.y += (w0 * v0.y + w1 * v1.y) + (w2 * v2.y + w3 * v3.y);
            acc.z += (w0 * v0.z + w1 * v1.z) + (w2 * v2.z + w3 * v3.z);
            acc.w += (w0 * v0.w + w1 * v1.w) + (w2 * v2.w + w3 * v3.w);
        }
    }
    for (; e < end; e++) {
        int s0 = g_csr[e];
        float d0 = g_dinv[s0];
        tacc += d0;
        float w0 = di * d0;
        if (lane < NF4) {
            float4 v0 = S[(size_t)s0 * NF4 + lane];
            acc.x += w0 * v0.x; acc.y += w0 * v0.y;
            acc.z += w0 * v0.z; acc.w += w0 * v0.w;
        }
    }
    if (lane < NF4) {
        acc.x = f2tf(acc.x); acc.y = f2tf(acc.y);
        acc.z = f2tf(acc.z); acc.w = f2tf(acc.w);
        ((float4*)dst)[(size_t)gw * NF4 + lane] = acc;
    }
    if (WRITE_T && lane == 0) g_t[gw] = tacc;
}

// ---------------- tf32 mma.sync GEMM, cp.async double buffered ----------------
// EPI 0: relu(+bias), tf32-rounded store to C, fused BN stats -> statp
// EPI 1: v = acc + bias + (dinv*t)*cvec; u = relu(v); NO C write.
//        Fused pool via smem staging + per-graph-segment atomics; BN2 stats -> statp.
template <int KF4, int KTILES, int EPI>
__global__ void __launch_bounds__(256) gemm_mma(const float* __restrict__ A,
                                                const float* __restrict__ B,
                                                const float* __restrict__ bias,
                                                const float* __restrict__ cvec,
                                                float* __restrict__ statp,
                                                float* __restrict__ C,
                                                const int* __restrict__ ib, int M) {
    extern __shared__ float Udyn[];     // EPI1 only: [128][129] staged relu(out2)
    __shared__ float As[2][128][20];
    __shared__ float Bs[2][16][136];
    __shared__ float sS[4][128];
    __shared__ float sQ[4][128];
    __shared__ int   sib[128];
    int tid = threadIdx.x, lane = tid & 31, wid = tid >> 5;
    int gid = lane >> 2, tig = lane & 3;
    int wm = wid & 3, wn = wid >> 2;
    int rbase = wm * 32, cbase = wn * 64;
    int row0 = blockIdx.x << 7;

    float cacc[2][8][4];
#pragma unroll
    for (int mi = 0; mi < 2; mi++)
#pragma unroll
        for (int ni = 0; ni < 8; ni++)
#pragma unroll
            for (int q = 0; q < 4; q++) cacc[mi][ni][q] = 0.f;

    int ar[2], akq[2], bk[2], bnq[2];
    uint32_t aaddr[2][2], baddr[2][2];
#pragma unroll
    for (int i = 0; i < 2; i++) {
        int idx = tid + i * 256;
        ar[i] = idx >> 2; akq[i] = idx & 3;
        bk[i] = idx >> 5; bnq[i] = idx & 31;
#pragma unroll
        for (int b = 0; b < 2; b++) {
            aaddr[b][i] = (uint32_t)__cvta_generic_to_shared(&As[b][ar[i]][akq[i] * 4]);
            baddr[b][i] = (uint32_t)__cvta_generic_to_shared(&Bs[b][bk[i]][bnq[i] * 4]);
        }
    }

    auto load_chunk = [&](int kc, int buf) {
#pragma unroll
        for (int i = 0; i < 2; i++) {
            int grow = row0 + ar[i];
            const float4* src = (const float4*)A +
                ((grow < M ? (size_t)grow : 0) * KF4 + kc * 4 + akq[i]);
            uint32_t ssz = (grow < M) ? 16u : 0u;
            CP_A16(aaddr[buf][i], src, ssz);
        }
#pragma unroll
        for (int i = 0; i < 2; i++) {
            const float4* src = (const float4*)B + ((size_t)(kc * 16 + bk[i]) * 32 + bnq[i]);
            CP_A16(baddr[buf][i], src, 16u);
        }
    };

    load_chunk(0, 0);
    CP_COMMIT();

    for (int kc = 0; kc < KTILES; kc++) {
        if (kc + 1 < KTILES) {
            load_chunk(kc + 1, (kc + 1) & 1);
            CP_COMMIT();
            asm volatile("cp.async.wait_group 1;" ::: "memory");
        } else {
            asm volatile("cp.async.wait_group 0;" ::: "memory");
        }
        __syncthreads();
        int buf = kc & 1;
#pragma unroll
        for (int ks = 0; ks < 2; ks++) {
            uint32_t af[2][4];
#pragma unroll
            for (int mi = 0; mi < 2; mi++) {
                int rr = rbase + mi * 16 + gid;
                af[mi][0] = __float_as_uint(As[buf][rr][ks * 8 + tig]);
                af[mi][1] = __float_as_uint(As[buf][rr + 8][ks * 8 + tig]);
                af[mi][2] = __float_as_uint(As[buf][rr][ks * 8 + tig + 4]);
                af[mi][3] = __float_as_uint(As[buf][rr + 8][ks * 8 + tig + 4]);
            }
            uint32_t bf[8][2];
#pragma unroll
            for (int ni = 0; ni < 8; ni++) {
                int nn = cbase + ni * 8 + gid;
                bf[ni][0] = __float_as_uint(Bs[buf][ks * 8 + tig][nn]);
                bf[ni][1] = __float_as_uint(Bs[buf][ks * 8 + tig + 4][nn]);
            }
#pragma unroll
            for (int mi = 0; mi < 2; mi++)
#pragma unroll
                for (int ni = 0; ni < 8; ni++) {
                    asm volatile(
                        "mma.sync.aligned.m16n8k8.row.col.f32.tf32.tf32.f32 "
                        "{%0,%1,%2,%3}, {%4,%5,%6,%7}, {%8,%9}, {%0,%1,%2,%3};"
                        : "+f"(cacc[mi][ni][0]), "+f"(cacc[mi][ni][1]),
                          "+f"(cacc[mi][ni][2]), "+f"(cacc[mi][ni][3])
                        : "r"(af[mi][0]), "r"(af[mi][1]), "r"(af[mi][2]), "r"(af[mi][3]),
                          "r"(bf[ni][0]), "r"(bf[ni][1]));
                }
        }
        __syncthreads();
    }

    float bs[8][2], cvv[8][2];
#pragma unroll
    for (int ni = 0; ni < 8; ni++) {
        int col = cbase + ni * 8 + tig * 2;
        bs[ni][0] = bias[col];
        bs[ni][1] = bias[col + 1];
        if (EPI == 1) { cvv[ni][0] = cvec[col]; cvv[ni][1] = cvec[col + 1]; }
    }

    if (EPI == 0) {
        float sacc[8][2], qacc[8][2];
#pragma unroll
        for (int ni = 0; ni < 8; ni++) {
            sacc[ni][0] = 0.f; sacc[ni][1] = 0.f;
            qacc[ni][0] = 0.f; qacc[ni][1] = 0.f;
        }
#pragma unroll
        for (int mi = 0; mi < 2; mi++) {
            int rA = row0 + rbase + mi * 16 + gid;
            int rB = rA + 8;
#pragma unroll
            for (int ni = 0; ni < 8; ni++) {
                int col = cbase + ni * 8 + tig * 2;
                float v0 = fmaxf(cacc[mi][ni][0] + bs[ni][0], 0.f);
                float v1 = fmaxf(cacc[mi][ni][1] + bs[ni][1], 0.f);
                float v2 = fmaxf(cacc[mi][ni][2] + bs[ni][0], 0.f);
                float v3 = fmaxf(cacc[mi][ni][3] + bs[ni][1], 0.f);
                if (rA < M) {
                    sacc[ni][0] += v0; qacc[ni][0] += v0 * v0;
                    sacc[ni][1] += v1; qacc[ni][1] += v1 * v1;
                    *(float2*)&C[(size_t)rA * 128 + col] = make_float2(f2tf(v0), f2tf(v1));
                }
                if (rB < M) {
                    sacc[ni][0] += v2; qacc[ni][0] += v2 * v2;
                    sacc[ni][1] += v3; qacc[ni][1] += v3 * v3;
                    *(float2*)&C[(size_t)rB * 128 + col] = make_float2(f2tf(v2), f2tf(v3));
                }
            }
        }
#pragma unroll
        for (int ni = 0; ni < 8; ni++)
#pragma unroll
            for (int j = 0; j < 2; j++) {
#pragma unroll
                for (int off = 4; off < 32; off <<= 1) {
                    sacc[ni][j] += __shfl_xor_sync(0xffffffffu, sacc[ni][j], off);
                    qacc[ni][j] += __shfl_xor_sync(0xffffffffu, qacc[ni][j], off);
                }
            }
        if (gid == 0) {
#pragma unroll
            for (int ni = 0; ni < 8; ni++) {
                int col = cbase + ni * 8 + tig * 2;
                sS[wm][col] = sacc[ni][0]; sS[wm][col + 1] = sacc[ni][1];
                sQ[wm][col] = qacc[ni][0]; sQ[wm][col + 1] = qacc[ni][1];
            }
        }
        __syncthreads();
        if (tid < 128) {
            float s = 0.f, q = 0.f;
#pragma unroll
            for (int w = 0; w < 4; w++) { s += sS[w][tid]; q += sQ[w][tid]; }
            atomicAdd(&statp[tid], s);
            atomicAdd(&statp[128 + tid], q);
        }
    } else {
        // EPI 1: stage relu(out2) to smem, then per-graph pooled reduction
#pragma unroll
        for (int mi = 0; mi < 2; mi++) {
            int lrA = rbase + mi * 16 + gid;
            int rA = row0 + lrA, rB = rA + 8;
            float sA = (rA < M) ? g_dinv[rA] * g_t[rA] : 0.f;
            float sB = (rB < M) ? g_dinv[rB] * g_t[rB] : 0.f;
#pragma unroll
            for (int ni = 0; ni < 8; ni++) {
                int col = cbase + ni * 8 + tig * 2;
                float v0 = fmaxf(cacc[mi][ni][0] + bs[ni][0] + sA * cvv[ni][0], 0.f);
                float v1 = fmaxf(cacc[mi][ni][1] + bs[ni][1] + sA * cvv[ni][1], 0.f);
                float v2 = fmaxf(cacc[mi][ni][2] + bs[ni][0] + sB * cvv[ni][0], 0.f);
                float v3 = fmaxf(cacc[mi][ni][3] + bs[ni][1] + sB * cvv[ni][1], 0.f);
                Udyn[lrA * 129 + col] = v0;
                Udyn[lrA * 129 + col + 1] = v1;
                Udyn[(lrA + 8) * 129 + col] = v2;
                Udyn[(lrA + 8) * 129 + col + 1] = v3;
            }
        }
        if (tid < 128) {
            int grow = row0 + tid;
            sib[tid] = (grow < M) ? ib[grow] : -1;
        }
        __syncthreads();
        int col = tid & 127, half = tid >> 7;
        int r0 = half * 64, r1 = r0 + 64;
        float s = 0.f, q = 0.f, mx = 0.f, mn = 0.f;
        int gcur = -1;
        for (int r = r0; r < r1; r++) {
            int g = sib[r];
            if (g < 0) break;   // trailing invalid rows only
            float u = Udyn[r * 129 + col];
            s += u; q += u * u;
            if (g != gcur) {
                if (gcur >= 0) {
                    atomicMax((int*)&g_smax[gcur * HF + col], __float_as_int(mx));
                    atomicMin((int*)&g_smin[gcur * HF + col], __float_as_int(mn));
                }
                gcur = g; mx = u; mn = u;
            } else {
                mx = fmaxf(mx, u); mn = fminf(mn, u);
            }
        }
        if (gcur >= 0) {
            atomicMax((int*)&g_smax[gcur * HF + col], __float_as_int(mx));
            atomicMin((int*)&g_smin[gcur * HF + col], __float_as_int(mn));
        }
        atomicAdd(&statp[col], s);
        atomicAdd(&statp[HF + col], q);
    }
}

// ---------------- FFMA2 GEMM (cell branch only) ----------------
template <int EPI, bool ALIGN4>
__global__ void __launch_bounds__(256, 2) gemm_t(const float* __restrict__ A,
                                                 const float* __restrict__ B,
                                                 const float* __restrict__ bias,
                                                 float* __restrict__ C,
                                                 float* __restrict__ statp,
                                                 int M, int K) {
    __shared__ float As[16][132];
    __shared__ float Bs[16][128];
    __shared__ float redS[16][128];
    __shared__ float redQ[16][128];
    int tid = threadIdx.x;
    int tx = tid & 15;
    int ty = tid >> 4;
    int row0 = blockIdx.x * 128;

    unsigned long long acc[8][4];
#pragma unroll
    for (int r = 0; r < 8; r++)
#pragma unroll
        for (int c = 0; c < 4; c++) acc[r][c] = 0ULL;

    for (int k0 = 0; k0 < K; k0 += 16) {
#pragma unroll
        for (int s = tid; s < 512; s += 256) {
            int r = s >> 2, kq = s & 3;
            int grow = row0 + r, gk = k0 + kq * 4;
            float4 v = make_float4(0.f, 0.f, 0.f, 0.f);
            if (grow < M) {
                const float* arow = A + (size_t)grow * K;
                if (gk + 3 < K) {
                    if (ALIGN4) {
                        v = *(const float4*)&arow[gk];
                    } else {
                        float2 v0 = *(const float2*)&arow[gk];
                        float2 v1 = *(const float2*)&arow[gk + 2];
                        v = make_float4(v0.x, v0.y, v1.x, v1.y);
                    }
                } else {
                    if (gk + 0 < K) v.x = arow[gk + 0];
                    if (gk + 1 < K) v.y = arow[gk + 1];
                    if (gk + 2 < K) v.z = arow[gk + 2];
                    if (gk + 3 < K) v.w = arow[gk + 3];
                }
            }
            As[kq * 4 + 0][r] = v.x;
            As[kq * 4 + 1][r] = v.y;
            As[kq * 4 + 2][r] = v.z;
            As[kq * 4 + 3][r] = v.w;
        }
#pragma unroll
        for (int s = tid; s < 512; s += 256) {
            int kk = s >> 5, nq = s & 31;
            int gk = k0 + kk;
            float4 v = make_float4(0.f, 0.f, 0.f, 0.f);
            if (gk < K) v = *(const float4*)&B[(size_t)gk * 128 + nq * 4];
            *(float4*)&Bs[kk][nq * 4] = v;
        }
        __syncthreads();
#pragma unroll
        for (int kk = 0; kk < 16; kk++) {
            float4 a0 = *(const float4*)&As[kk][ty * 8];
            float4 a1 = *(const float4*)&As[kk][ty * 8 + 4];
            ulonglong2 bA = *(const ulonglong2*)&Bs[kk][tx * 8];
            ulonglong2 bB = *(const ulonglong2*)&Bs[kk][tx * 8 + 4];
            unsigned long long bv[4] = {bA.x, bA.y, bB.x, bB.y};
            float av[8] = {a0.x, a0.y, a0.z, a0.w, a1.x, a1.y, a1.z, a1.w};
#pragma unroll
            for (int r = 0; r < 8; r++) {
                unsigned long long ap;
                unsigned int ai = __float_as_uint(av[r]);
                asm("mov.b64 %0, {%1, %1};" : "=l"(ap) : "r"(ai));
#pragma unroll
                for (int c = 0; c < 4; c++) {
                    asm("fma.rn.f32x2 %0, %1, %2, %3;"
                        : "=l"(acc[r][c]) : "l"(ap), "l"(bv[c]), "l"(acc[r][c]));
                }
            }
        }
        __syncthreads();
    }

    float bv0[8];
#pragma unroll
    for (int c = 0; c < 8; c++) bv0[c] = bias[tx * 8 + c];
    float s8[8], q8[8];
    if (EPI == 2) {
#pragma unroll
        for (int c = 0; c < 8; c++) { s8[c] = 0.f; q8[c] = 0.f; }
    }
#pragma unroll
    for (int r = 0; r < 8; r++) {
        int grow = row0 + ty * 8 + r;
        if (grow < M) {
            float o[8];
#pragma unroll
            for (int c = 0; c < 4; c++) {
                float lo, hi;
                asm("mov.b64 {%0, %1}, %2;" : "=f"(lo), "=f"(hi) : "l"(acc[r][c]));
                o[2 * c] = lo; o[2 * c + 1] = hi;
            }
#pragma unroll
            for (int c = 0; c < 8; c++) {
                float v = o[c] + bv0[c];
                if (EPI == 2) v = tanhf(v);
                if (EPI == 3) v = fmaxf(v, 0.f);
                if (EPI == 2) { s8[c] += v; q8[c] += v * v; }
                o[c] = v;
            }
            *(float4*)&C[(size_t)grow * 128 + tx * 8] = make_float4(o[0], o[1], o[2], o[3]);
            *(float4*)&C[(size_t)grow * 128 + tx * 8 + 4] = make_float4(o[4], o[5], o[6], o[7]);
        }
    }
    if (EPI == 2) {
#pragma unroll
        for (int c = 0; c < 8; c++) { redS[ty][tx * 8 + c] = s8[c]; redQ[ty][tx * 8 + c] = q8[c]; }
        __syncthreads();
        if (tid < 128) {
            float s = 0.f, q = 0.f;
#pragma unroll
            for (int t = 0; t < 16; t++) { s += redS[t][tid]; q += redQ[t][tid]; }
            atomicAdd(&statp[tid], s);
            atomicAdd(&statp[128 + tid], q);
        }
    }
}

// ---------------- parallel fold BN1 into W2: one block per output column ----------------
__global__ void __launch_bounds__(128) k_fold1p(const float* __restrict__ g1,
                                                const float* __restrict__ be1,
                                                const float* __restrict__ W2) {
    __shared__ float red[128];
    int n = blockIdx.x;
    int k = threadIdx.x;
    float mu = g_stat1[k] * (1.0f / NN);
    float var = g_stat1[HF + k] * (1.0f / NN) - mu * mu;
    float sck = g1[k] * rsqrtf(var + BN_EPS);
    float shk = be1[k] - mu * sck;
    float w = W2[k * HF + n];
    g_W2p[k * HF + n] = f2tf(sck * w);
    red[k] = shk * w;
    __syncthreads();
    for (int o = 64; o > 0; o >>= 1) {
        if (k < o) red[k] += red[k + o];
        __syncthreads();
    }
    if (k == 0) g_c2[n] = red[0];
}

// ---------------- fold cell BN into Wc2 (zeroes g_statc) ----------------
__global__ void k_foldc(const float* __restrict__ gc1, const float* __restrict__ bec1,
                        const float* __restrict__ Wc2, const float* __restrict__ bc2) {
    __shared__ float sc[HF], sh[HF];
    int n = threadIdx.x;
    float mu = g_statc[n] * (1.0f / NG);
    float var = g_statc[HF + n] * (1.0f / NG) - mu * mu;
    g_statc[n] = 0.f; g_statc[HF + n] = 0.f;
    float s = gc1[n] * rsqrtf(var + BN_EPS);
    sc[n] = s;
    sh[n] = bec1[n] - mu * s;
    __syncthreads();
    float c = 0.f;
#pragma unroll 8
    for (int k = 0; k < HF; k++) {
        float w = Wc2[k * HF + n];
        g_Wc2p[k * HF + n] = sc[k] * w;
        c += sh[k] * w;
    }
    g_bc2p[n] = bc2[n] + c;
}

// ---------------- final select with BN2 scale computed inline ----------------
__global__ void k_final(const float* __restrict__ g2, const float* __restrict__ be2,
                        float* __restrict__ out) {
    int idx = blockIdx.x * blockDim.x + threadIdx.x;
    if (idx < 2 * HF) g_stat1[idx] = 0.f;   // restore zeros for next replay
    if (idx >= NG * HF) return;
    int k = idx & 127;
    float mu = g_stat2[k] * (1.0f / NN);
    float var = g_stat2[HF + k] * (1.0f / NN) - mu * mu;
    float s = g2[k] * rsqrtf(var + BN_EPS);
    float sh = be2[k] - mu * s;
    float mx = g_smax[idx];
    float r;
    if (mx == neg_inf()) {
        r = neg_inf();
    } else {
        float v = (s >= 0.f) ? mx : g_smin[idx];
        r = s * v + sh;
    }
    out[idx] = r;
}

// ---------------- host ----------------
extern "C" void kernel_launch(void* const* d_in, const int* in_sizes, int n_in,
                              void* d_out, int out_size) {
    const float* drug = (const float*)d_in[0];
    const int* ei = (const int*)d_in[1];
    const int* ib = (const int*)d_in[2];
    const float* gexpr = (const float*)d_in[3];
    const float* W1 = (const float*)d_in[4];
    const float* b1 = (const float*)d_in[5];
    const float* g1 = (const float*)d_in[6];
    const float* be1 = (const float*)d_in[7];
    const float* W2 = (const float*)d_in[8];
    const float* b2 = (const float*)d_in[9];
    const float* g2 = (const float*)d_in[10];
    const float* be2 = (const float*)d_in[11];
    const float* Wc1 = (const float*)d_in[12];
    const float* bc1 = (const float*)d_in[13];
    const float* gc1 = (const float*)d_in[14];
    const float* bec1 = (const float*)d_in[15];
    const float* Wc2 = (const float*)d_in[16];
    const float* bc2 = (const float*)d_in[17];
    float* out = (float*)d_out;

    float *dpp, *hp, *xp, *yp, *cellp, *stat1p, *stat2p, *statcp, *W1pp, *W2pp, *c2p, *Wc2pp, *bc2pp;
    cudaGetSymbolAddress((void**)&dpp, g_dp);
    cudaGetSymbolAddress((void**)&hp, g_h);
    cudaGetSymbolAddress((void**)&xp, g_x);
    cudaGetSymbolAddress((void**)&yp, g_y);
    cudaGetSymbolAddress((void**)&cellp, g_cell);
    cudaGetSymbolAddress((void**)&stat1p, g_stat1);
    cudaGetSymbolAddress((void**)&stat2p, g_stat2);
    cudaGetSymbolAddress((void**)&statcp, g_statc);
    cudaGetSymbolAddress((void**)&W1pp, g_W1p);
    cudaGetSymbolAddress((void**)&W2pp, g_W2p);
    cudaGetSymbolAddress((void**)&c2p, g_c2);
    cudaGetSymbolAddress((void**)&Wc2pp, g_Wc2p);
    cudaGetSymbolAddress((void**)&bc2pp, g_bc2p);

    const int USMEM = 128 * 129 * 4;
    cudaFuncSetAttribute(gemm_mma<32, 8, 1>, cudaFuncAttributeMaxDynamicSharedMemorySize, USMEM);

    static cudaStream_t sB = nullptr, sC = nullptr, sD = nullptr;
    static cudaEvent_t eStart = nullptr, e0 = nullptr, eB = nullptr, eC = nullptr,
                       eF = nullptr, eGB = nullptr, eG1 = nullptr, eD = nullptr;
    if (!sB) {
        cudaStreamCreateWithFlags(&sB, cudaStreamNonBlocking);
        cudaStreamCreateWithFlags(&sC, cudaStreamNonBlocking);
        cudaStreamCreateWithFlags(&sD, cudaStreamNonBlocking);
        cudaEventCreateWithFlags(&eStart, cudaEventDisableTiming);
        cudaEventCreateWithFlags(&e0, cudaEventDisableTiming);
        cudaEventCreateWithFlags(&eB, cudaEventDisableTiming);
        cudaEventCreateWithFlags(&eC, cudaEventDisableTiming);
        cudaEventCreateWithFlags(&eF, cudaEventDisableTiming);
        cudaEventCreateWithFlags(&eGB, cudaEventDisableTiming);
        cudaEventCreateWithFlags(&eG1, cudaEventDisableTiming);
        cudaEventCreateWithFlags(&eD, cudaEventDisableTiming);
    }

    // origin stream: fork anchor
    k_nop<<<1, 32>>>();
    cudaEventRecord(eStart, 0);

    // branch C (forked): pool-accumulator init (+stat2 zero) + cell branch
    cudaStreamWaitEvent(sC, eStart, 0);
    k_ginit<<<(NG * HF + 255) / 256, 256, 0, sC>>>();
    cudaEventRecord(eGB, sC);
    gemm_t<2, false><<<(NG + 127) / 128, 256, 0, sC>>>(gexpr, Wc1, bc1, cellp, statcp, NG, KCELL);
    k_foldc<<<1, HF, 0, sC>>>(gc1, bec1, Wc2, bc2);
    gemm_t<3, true><<<(NG + 127) / 128, 256, 0, sC>>>(cellp, Wc2pp, bc2pp, out + NG * HF, nullptr, NG, HF);
    cudaEventRecord(eC, sC);

    // branch D (forked): drug padding + W1 pad (no deps, overlaps k_cnt)
    cudaStreamWaitEvent(sD, eStart, 0);
    k_padDrug<<<(NN * 40 + 255) / 256, 256, 0, sD>>>(drug);
    k_padW<<<(KPAD * HF + 255) / 256, 256, 0, sD>>>(W1);
    cudaEventRecord(eD, sD);

    // origin: indegree count -> dinv
    k_cnt<<<(NE + 255) / 256, 256>>>(ei);
    cudaEventRecord(e0, 0);
    k_dinv<<<(NN + 255) / 256, 256>>>();

    // branch B: CSR build
    cudaStreamWaitEvent(sB, e0, 0);
    k_scan1<<<SCAN_NB, 256, 0, sB>>>();
    k_scan3<<<(NN + 255) / 256, 256, 0, sB>>>();
    k_fill<<<(NE + 255) / 256, 256, 0, sB>>>(ei);
    cudaEventRecord(eB, sB);

    // join CSR + padding; layer 1: gather -> gemm1 (relu + bias + stats fused)
    cudaStreamWaitEvent(0, eB, 0);
    cudaStreamWaitEvent(0, eD, 0);
    k_gather<20, true, true><<<(NN * 32 + 255) / 256, 256>>>(dpp, hp);
    gemm_mma<20, 5, 0><<<(NN + 127) / 128, 256>>>(hp, W1pp, b1, nullptr, stat1p, xp, nullptr, NN);
    cudaEventRecord(eG1, 0);

    // stream B: parallel fold1 concurrent with gather2
    cudaStreamWaitEvent(sB, eG1, 0);
    k_fold1p<<<HF, HF, 0, sB>>>(g1, be1, W2);
    cudaEventRecord(eF, sB);

    // layer 2: gather relu(out1) -> join fold + pool-init -> gemm2 (pool fused)
    k_gather<32, false, false><<<(NN * 32 + 255) / 256, 256>>>(xp, yp);
    cudaStreamWaitEvent(0, eF, 0);
    cudaStreamWaitEvent(0, eGB, 0);
    gemm_mma<32, 8, 1><<<(NN + 127) / 128, 256, USMEM>>>(yp, W2pp, b2, c2p, stat2p, nullptr, ib, NN);

    // final select (BN2 fold inline)
    k_final<<<(NG * HF + 255) / 256, 256>>>(g2, be2, out);

    cudaStreamWaitEvent(0, eC, 0);
}

// round 15
// speedup vs baseline: 1.0494x; 1.0494x over previous
#include <cuda_runtime.h>
#include <cuda_fp16.h>
#include <cstdint>

#define NN 200000
#define NE 800000
#define NG 4096
#define KDRUG 78
#define KPAD 80
#define KCELL 954
#define HF 128
#define BN_EPS 1e-5f
#define SCAN_NB 98   // ceil(NN/2048)

// ---------------- scratch (zero-init at load; every run restores zeros) ----------------
__device__ int    g_cnt[NN];
__device__ int    g_fill[NN];
__device__ int    g_off[NN + 1];
__device__ int    g_bsum[SCAN_NB];
__device__ int    g_csr[NE];
__device__ float  g_dinv[NN];
__device__ float  g_t[NN];
__device__ float  g_dp[(size_t)NN * KPAD];
__device__ float  g_h[(size_t)NN * KPAD];    // agg1 [NN,80] (tf32-rounded)
__device__ float  g_y[(size_t)NN * HF];      // agg2 [NN,128] (tf32-rounded)
__device__ __half g_x16[(size_t)NN * HF];    // relu(out1) in fp16 (same 10-bit mantissa as tf32)
__device__ float  g_W1p[KPAD * HF];          // W1 padded [80][128] (tf32-rounded)
__device__ float  g_W2p[HF * HF];            // folded W2 [k][n] (tf32-rounded)
__device__ float  g_stat1[2 * HF];
__device__ float  g_stat2[2 * HF];
__device__ float  g_statc[2 * HF];
__device__ float  g_c2[HF];
__device__ float  g_Wc2p[HF * HF];
__device__ float  g_bc2p[HF];
__device__ float  g_smax[NG * HF];
__device__ float  g_smin[NG * HF];
__device__ float  g_cell[(size_t)NG * HF];

__device__ __forceinline__ float neg_inf() { return __int_as_float(0xff800000); }
__device__ __forceinline__ float pos_inf() { return __int_as_float(0x7f800000); }
__device__ __forceinline__ float f2tf(float f) {
    uint32_t u;
    asm("cvt.rna.tf32.f32 %0, %1;" : "=r"(u) : "f"(f));
    return __uint_as_float(u);
}

#define CP_A16(saddr, gptr, ssz) \
    asm volatile("cp.async.ca.shared.global [%0], [%1], 16, %2;" :: "r"(saddr), "l"(gptr), "r"(ssz))
#define CP_COMMIT() asm volatile("cp.async.commit_group;" ::: "memory")

// ---------------- tiny no-op kernel (capture fork anchor) ----------------
__global__ void k_nop() {}

// ---------------- edge count (g_cnt arrives zeroed) ----------------
__global__ void k_cnt(const int* __restrict__ ei) {
    int e = blockIdx.x * blockDim.x + threadIdx.x;
    if (e < NE) atomicAdd(&g_cnt[ei[NE + e]], 1);
}

// ---------------- init pool accumulators (-inf / +inf) + zero stat2 ----------------
__global__ void k_ginit() {
    int idx = blockIdx.x * blockDim.x + threadIdx.x;
    if (idx < 2 * HF) g_stat2[idx] = 0.f;   // gemm2 ordered after this via eGB
    if (idx < NG * HF) { g_smax[idx] = neg_inf(); g_smin[idx] = pos_inf(); }
}

// ---------------- CSR scan ----------------
__global__ void __launch_bounds__(256) k_scan1() {
    __shared__ int wsum[8];
    __shared__ int woff[8];
    int t = threadIdx.x;
    int base = blockIdx.x * 2048 + t * 8;
    int v[8];
    int run = 0;
#pragma unroll
    for (int j = 0; j < 8; j++) {
        int idx = base + j;
        int c = (idx < NN) ? g_cnt[idx] : 0;
        v[j] = run;
        run += c;
    }
    int lane = t & 31, w = t >> 5;
    int x = run;
#pragma unroll
    for (int o = 1; o < 32; o <<= 1) {
        int y = __shfl_up_sync(0xffffffffu, x, o);
        if (lane >= o) x += y;
    }
    if (lane == 31) wsum[w] = x;
    __syncthreads();
    if (t == 0) {
        int r = 0;
#pragma unroll
        for (int k = 0; k < 8; k++) { woff[k] = r; r += wsum[k]; }
        g_bsum[blockIdx.x] = r;
    }
    __syncthreads();
    int texc = x - run + woff[w];
#pragma unroll
    for (int j = 0; j < 8; j++) {
        int idx = base + j;
        if (idx < NN) g_off[idx] = texc + v[j];
    }
}

__global__ void __launch_bounds__(256) k_scan3() {
    __shared__ int raw[SCAN_NB];
    __shared__ int pref[SCAN_NB];
    int t = threadIdx.x;
    if (t < SCAN_NB) raw[t] = g_bsum[t];
    __syncthreads();
    if (t == 0) {
        int r = 0;
#pragma unroll 7
        for (int b = 0; b < SCAN_NB; b++) { pref[b] = r; r += raw[b]; }
    }
    __syncthreads();
    int i = blockIdx.x * blockDim.x + t;
    if (i < NN) g_off[i] += pref[i >> 11];
    if (i == 0) g_off[NN] = NE;
}

__global__ void k_fill(const int* __restrict__ ei) {
    int e = blockIdx.x * blockDim.x + threadIdx.x;
    if (e < NE) {
        int d = ei[NE + e];
        int pos = g_off[d] + atomicAdd(&g_fill[d], 1);
        g_csr[pos] = ei[e];
    }
}

// ---------------- pad W1 [78,128] -> [80,128], tf32-rounded ----------------
__global__ void k_padW(const float* __restrict__ W1) {
    int idx = blockIdx.x * blockDim.x + threadIdx.x;
    if (idx >= KPAD * HF) return;
    int row = idx >> 7;
    g_W1p[idx] = (row < KDRUG) ? f2tf(W1[idx]) : 0.f;
}

// ---------------- pad drug + compute dinv (fused) ----------------
__global__ void k_pad(const float* __restrict__ drug) {
    int idx = blockIdx.x * blockDim.x + threadIdx.x;
    if (idx < NN) g_dinv[idx] = rsqrtf((float)(1 + g_cnt[idx]));
    if (idx >= NN * 40) return;
    int i = idx / 40, s = idx - i * 40;
    float2 v = make_float2(0.f, 0.f);
    if (s < 39) v = ((const float2*)drug)[(size_t)i * 39 + s];
    ((float2*)g_dp)[idx] = v;
}

// ---------------- CSR gather (80-dim float path, layer 1), 4x unrolled ----------------
__global__ void __launch_bounds__(256) k_gather1(const float* __restrict__ src,
                                                 float* __restrict__ dst) {
    int gw = (blockIdx.x * 256 + threadIdx.x) >> 5;
    if (gw >= NN) return;
    int lane = threadIdx.x & 31;
    if (lane == 0) { g_cnt[gw] = 0; g_fill[gw] = 0; }   // restore zeros for next replay
    float di = g_dinv[gw];
    int beg = g_off[gw], end = g_off[gw + 1];
    const float4* S = (const float4*)src;
    const int NF4 = 20;
    float4 acc = make_float4(0.f, 0.f, 0.f, 0.f);
    if (lane < NF4) {
        float4 v = S[(size_t)gw * NF4 + lane];
        float a = di * di;
        acc = make_float4(v.x * a, v.y * a, v.z * a, v.w * a);
    }
    float tacc = di;
    int e = beg;
    for (; e + 3 < end; e += 4) {
        int s0 = g_csr[e], s1 = g_csr[e + 1], s2 = g_csr[e + 2], s3 = g_csr[e + 3];
        float d0 = g_dinv[s0], d1 = g_dinv[s1], d2 = g_dinv[s2], d3 = g_dinv[s3];
        tacc += (d0 + d1) + (d2 + d3);
        if (lane < NF4) {
            float4 v0 = S[(size_t)s0 * NF4 + lane];
            float4 v1 = S[(size_t)s1 * NF4 + lane];
            float4 v2 = S[(size_t)s2 * NF4 + lane];
            float4 v3 = S[(size_t)s3 * NF4 + lane];
            float w0 = di * d0, w1 = di * d1, w2 = di * d2, w3 = di * d3;
            acc.x += (w0 * v0.x + w1 * v1.x) + (w2 * v2.x + w3 * v3.x);
            acc.y += (w0 * v0.y + w1 * v1.y) + (w2 * v2.y + w3 * v3.y);
            acc.z += (w0 * v0.z + w1 * v1.z) + (w2 * v2.z + w3 * v3.z);
            acc.w += (w0 * v0.w + w1 * v1.w) + (w2 * v2.w + w3 * v3.w);
        }
    }
    for (; e < end; e++) {
        int s0 = g_csr[e];
        float d0 = g_dinv[s0];
        tacc += d0;
        float w0 = di * d0;
        if (lane < NF4) {
            float4 v0 = S[(size_t)s0 * NF4 + lane];
            acc.x += w0 * v0.x; acc.y += w0 * v0.y;
            acc.z += w0 * v0.z; acc.w += w0 * v0.w;
        }
    }
    if (lane < NF4) {
        acc.x = f2tf(acc.x); acc.y = f2tf(acc.y);
        acc.z = f2tf(acc.z); acc.w = f2tf(acc.w);
        ((float4*)dst)[(size_t)gw * NF4 + lane] = acc;
    }
    if (lane == 0) g_t[gw] = tacc;
}

// ---------------- CSR gather (128-dim fp16 source, layer 2), 4x unrolled ----------------
// Each lane handles 4 columns = one uint2 (4 halves) per row. fp32 accumulation.
__global__ void __launch_bounds__(256) k_gather2(const __half* __restrict__ src,
                                                 float* __restrict__ dst) {
    int gw = (blockIdx.x * 256 + threadIdx.x) >> 5;
    if (gw >= NN) return;
    int lane = threadIdx.x & 31;
    float di = g_dinv[gw];
    int beg = g_off[gw], end = g_off[gw + 1];
    const uint2* S = (const uint2*)src;   // 4 halves per uint2; 32 per row
    auto cvt = [](uint2 u, float4& f) {
        __half2 h0 = *(__half2*)&u.x;
        __half2 h1 = *(__half2*)&u.y;
        float2 a = __half22float2(h0);
        float2 b = __half22float2(h1);
        f = make_float4(a.x, a.y, b.x, b.y);
    };
    float4 acc;
    {
        uint2 u = S[(size_t)gw * 32 + lane];
        float4 v; cvt(u, v);
        float a = di * di;
        acc = make_float4(v.x * a, v.y * a, v.z * a, v.w * a);
    }
    int e = beg;
    for (; e + 3 < end; e += 4) {
        int s0 = g_csr[e], s1 = g_csr[e + 1], s2 = g_csr[e + 2], s3 = g_csr[e + 3];
        float d0 = g_dinv[s0], d1 = g_dinv[s1], d2 = g_dinv[s2], d3 = g_dinv[s3];
        uint2 u0 = S[(size_t)s0 * 32 + lane];
        uint2 u1 = S[(size_t)s1 * 32 + lane];
        uint2 u2 = S[(size_t)s2 * 32 + lane];
        uint2 u3 = S[(size_t)s3 * 32 + lane];
        float4 v0, v1, v2, v3;
        cvt(u0, v0); cvt(u1, v1); cvt(u2, v2); cvt(u3, v3);
        float w0 = di * d0, w1 = di * d1, w2 = di * d2, w3 = di * d3;
        acc.x += (w0 * v0.x + w1 * v1.x) + (w2 * v2.x + w3 * v3.x);
        acc.y += (w0 * v0.y + w1 * v1.y) + (w2 * v2.y + w3 * v3.y);
        acc.z += (w0 * v0.z + w1 * v1.z) + (w2 * v2.z + w3 * v3.z);
        acc.w += (w0 * v0.w + w1 * v1.w) + (w2 * v2.w + w3 * v3.w);
    }
    for (; e < end; e++) {
        int s0 = g_csr[e];
        float w0 = di * g_dinv[s0];
        uint2 u0 = S[(size_t)s0 * 32 + lane];
        float4 v0; cvt(u0, v0);
        acc.x += w0 * v0.x; acc.y += w0 * v0.y;
        acc.z += w0 * v0.z; acc.w += w0 * v0.w;
    }
    acc.x = f2tf(acc.x); acc.y = f2tf(acc.y);
    acc.z = f2tf(acc.z); acc.w = f2tf(acc.w);
    ((float4*)dst)[(size_t)gw * 32 + lane] = acc;
}

// ---------------- tf32 mma.sync GEMM, cp.async double buffered ----------------
// EPI 0: relu(+bias), fp16 store to C16, fused BN stats -> statp
// EPI 1: v = acc + bias + (dinv*t)*cvec; u = relu(v); NO gmem matrix write.
//        Fused pool via smem staging + per-graph-segment atomics; BN2 stats -> statp.
template <int KF4, int KTILES, int EPI>
__global__ void __launch_bounds__(256) gemm_mma(const float* __restrict__ A,
                                                const float* __restrict__ B,
                                                const float* __restrict__ bias,
                                                const float* __restrict__ cvec,
                                                float* __restrict__ statp,
                                                __half* __restrict__ C16,
                                                const int* __restrict__ ib, int M) {
    extern __shared__ float Udyn[];     // EPI1 only: [128][129] staged relu(out2)
    __shared__ float As[2][128][20];
    __shared__ float Bs[2][16][136];
    __shared__ float sS[4][128];
    __shared__ float sQ[4][128];
    __shared__ int   sib[128];
    int tid = threadIdx.x, lane = tid & 31, wid = tid >> 5;
    int gid = lane >> 2, tig = lane & 3;
    int wm = wid & 3, wn = wid >> 2;
    int rbase = wm * 32, cbase = wn * 64;
    int row0 = blockIdx.x << 7;

    float cacc[2][8][4];
#pragma unroll
    for (int mi = 0; mi < 2; mi++)
#pragma unroll
        for (int ni = 0; ni < 8; ni++)
#pragma unroll
            for (int q = 0; q < 4; q++) cacc[mi][ni][q] = 0.f;

    int ar[2], akq[2], bk[2], bnq[2];
    uint32_t aaddr[2][2], baddr[2][2];
#pragma unroll
    for (int i = 0; i < 2; i++) {
        int idx = tid + i * 256;
        ar[i] = idx >> 2; akq[i] = idx & 3;
        bk[i] = idx >> 5; bnq[i] = idx & 31;
#pragma unroll
        for (int b = 0; b < 2; b++) {
            aaddr[b][i] = (uint32_t)__cvta_generic_to_shared(&As[b][ar[i]][akq[i] * 4]);
            baddr[b][i] = (uint32_t)__cvta_generic_to_shared(&Bs[b][bk[i]][bnq[i] * 4]);
        }
    }

    auto load_chunk = [&](int kc, int buf) {
#pragma unroll
        for (int i = 0; i < 2; i++) {
            int grow = row0 + ar[i];
            const float4* src = (const float4*)A +
                ((grow < M ? (size_t)grow : 0) * KF4 + kc * 4 + akq[i]);
            uint32_t ssz = (grow < M) ? 16u : 0u;
            CP_A16(aaddr[buf][i], src, ssz);
        }
#pragma unroll
        for (int i = 0; i < 2; i++) {
            const float4* src = (const float4*)B + ((size_t)(kc * 16 + bk[i]) * 32 + bnq[i]);
            CP_A16(baddr[buf][i], src, 16u);
        }
    };

    load_chunk(0, 0);
    CP_COMMIT();

    for (int kc = 0; kc < KTILES; kc++) {
        if (kc + 1 < KTILES) {
            load_chunk(kc + 1, (kc + 1) & 1);
            CP_COMMIT();
            asm volatile("cp.async.wait_group 1;" ::: "memory");
        } else {
            asm volatile("cp.async.wait_group 0;" ::: "memory");
        }
        __syncthreads();
        int buf = kc & 1;
#pragma unroll
        for (int ks = 0; ks < 2; ks++) {
            uint32_t af[2][4];
#pragma unroll
            for (int mi = 0; mi < 2; mi++) {
                int rr = rbase + mi * 16 + gid;
                af[mi][0] = __float_as_uint(As[buf][rr][ks * 8 + tig]);
                af[mi][1] = __float_as_uint(As[buf][rr + 8][ks * 8 + tig]);
                af[mi][2] = __float_as_uint(As[buf][rr][ks * 8 + tig + 4]);
                af[mi][3] = __float_as_uint(As[buf][rr + 8][ks * 8 + tig + 4]);
            }
            uint32_t bf[8][2];
#pragma unroll
            for (int ni = 0; ni < 8; ni++) {
                int nn = cbase + ni * 8 + gid;
                bf[ni][0] = __float_as_uint(Bs[buf][ks * 8 + tig][nn]);
                bf[ni][1] = __float_as_uint(Bs[buf][ks * 8 + tig + 4][nn]);
            }
#pragma unroll
            for (int mi = 0; mi < 2; mi++)
#pragma unroll
                for (int ni = 0; ni < 8; ni++) {
                    asm volatile(
                        "mma.sync.aligned.m16n8k8.row.col.f32.tf32.tf32.f32 "
                        "{%0,%1,%2,%3}, {%4,%5,%6,%7}, {%8,%9}, {%0,%1,%2,%3};"
                        : "+f"(cacc[mi][ni][0]), "+f"(cacc[mi][ni][1]),
                          "+f"(cacc[mi][ni][2]), "+f"(cacc[mi][ni][3])
                        : "r"(af[mi][0]), "r"(af[mi][1]), "r"(af[mi][2]), "r"(af[mi][3]),
                          "r"(bf[ni][0]), "r"(bf[ni][1]));
                }
        }
        __syncthreads();
    }

    float bs[8][2], cvv[8][2];
#pragma unroll
    for (int ni = 0; ni < 8; ni++) {
        int col = cbase + ni * 8 + tig * 2;
        bs[ni][0] = bias[col];
        bs[ni][1] = bias[col + 1];
        if (EPI == 1) { cvv[ni][0] = cvec[col]; cvv[ni][1] = cvec[col + 1]; }
    }

    if (EPI == 0) {
        float sacc[8][2], qacc[8][2];
#pragma unroll
        for (int ni = 0; ni < 8; ni++) {
            sacc[ni][0] = 0.f; sacc[ni][1] = 0.f;
            qacc[ni][0] = 0.f; qacc[ni][1] = 0.f;
        }
#pragma unroll
        for (int mi = 0; mi < 2; mi++) {
            int rA = row0 + rbase + mi * 16 + gid;
            int rB = rA + 8;
#pragma unroll
            for (int ni = 0; ni < 8; ni++) {
                int col = cbase + ni * 8 + tig * 2;
                float v0 = fmaxf(cacc[mi][ni][0] + bs[ni][0], 0.f);
                float v1 = fmaxf(cacc[mi][ni][1] + bs[ni][1], 0.f);
                float v2 = fmaxf(cacc[mi][ni][2] + bs[ni][0], 0.f);
                float v3 = fmaxf(cacc[mi][ni][3] + bs[ni][1], 0.f);
                if (rA < M) {
                    sacc[ni][0] += v0; qacc[ni][0] += v0 * v0;
                    sacc[ni][1] += v1; qacc[ni][1] += v1 * v1;
                    ((__half2*)C16)[(size_t)rA * 64 + (col >> 1)] = __floats2half2_rn(v0, v1);
                }
                if (rB < M) {
                    sacc[ni][0] += v2; qacc[ni][0] += v2 * v2;
                    sacc[ni][1] += v3; qacc[ni][1] += v3 * v3;
                    ((__half2*)C16)[(size_t)rB * 64 + (col >> 1)] = __floats2half2_rn(v2, v3);
                }
            }
        }
#pragma unroll
        for (int ni = 0; ni < 8; ni++)
#pragma unroll
            for (int j = 0; j < 2; j++) {
#pragma unroll
                for (int off = 4; off < 32; off <<= 1) {
                    sacc[ni][j] += __shfl_xor_sync(0xffffffffu, sacc[ni][j], off);
                    qacc[ni][j] += __shfl_xor_sync(0xffffffffu, qacc[ni][j], off);
                }
            }
        if (gid == 0) {
#pragma unroll
            for (int ni = 0; ni < 8; ni++) {
                int col = cbase + ni * 8 + tig * 2;
                sS[wm][col] = sacc[ni][0]; sS[wm][col + 1] = sacc[ni][1];
                sQ[wm][col] = qacc[ni][0]; sQ[wm][col + 1] = qacc[ni][1];
            }
        }
        __syncthreads();
        if (tid < 128) {
            float s = 0.f, q = 0.f;
#pragma unroll
            for (int w = 0; w < 4; w++) { s += sS[w][tid]; q += sQ[w][tid]; }
            atomicAdd(&statp[tid], s);
            atomicAdd(&statp[128 + tid], q);
        }
    } else {
        // EPI 1: stage relu(out2) to smem, then per-graph pooled reduction
#pragma unroll
        for (int mi = 0; mi < 2; mi++) {
            int lrA = rbase + mi * 16 + gid;
            int rA = row0 + lrA, rB = rA + 8;
            float sA = (rA < M) ? g_dinv[rA] * g_t[rA] : 0.f;
            float sB = (rB < M) ? g_dinv[rB] * g_t[rB] : 0.f;
#pragma unroll
            for (int ni = 0; ni < 8; ni++) {
                int col = cbase + ni * 8 + tig * 2;
                float v0 = fmaxf(cacc[mi][ni][0] + bs[ni][0] + sA * cvv[ni][0], 0.f);
                float v1 = fmaxf(cacc[mi][ni][1] + bs[ni][1] + sA * cvv[ni][1], 0.f);
                float v2 = fmaxf(cacc[mi][ni][2] + bs[ni][0] + sB * cvv[ni][0], 0.f);
                float v3 = fmaxf(cacc[mi][ni][3] + bs[ni][1] + sB * cvv[ni][1], 0.f);
                Udyn[lrA * 129 + col] = v0;
                Udyn[lrA * 129 + col + 1] = v1;
                Udyn[(lrA + 8) * 129 + col] = v2;
                Udyn[(lrA + 8) * 129 + col + 1] = v3;
            }
        }
        if (tid < 128) {
            int grow = row0 + tid;
            sib[tid] = (grow < M) ? ib[grow] : -1;
        }
        __syncthreads();
        int col = tid & 127, half = tid >> 7;
        int r0 = half * 64, r1 = r0 + 64;
        float s = 0.f, q = 0.f, mx = 0.f, mn = 0.f;
        int gcur = -1;
        for (int r = r0; r < r1; r++) {
            int g = sib[r];
            if (g < 0) break;   // trailing invalid rows only
            float u = Udyn[r * 129 + col];
            s += u; q += u * u;
            if (g != gcur) {
                if (gcur >= 0) {
                    atomicMax((int*)&g_smax[gcur * HF + col], __float_as_int(mx));
                    atomicMin((int*)&g_smin[gcur * HF + col], __float_as_int(mn));
                }
                gcur = g; mx = u; mn = u;
            } else {
                mx = fmaxf(mx, u); mn = fminf(mn, u);
            }
        }
        if (gcur >= 0) {
            atomicMax((int*)&g_smax[gcur * HF + col], __float_as_int(mx));
            atomicMin((int*)&g_smin[gcur * HF + col], __float_as_int(mn));
        }
        atomicAdd(&statp[col], s);
        atomicAdd(&statp[HF + col], q);
    }
}

// ---------------- FFMA2 GEMM (cell branch only) ----------------
template <int EPI, bool ALIGN4>
__global__ void __launch_bounds__(256, 2) gemm_t(const float* __restrict__ A,
                                                 const float* __restrict__ B,
                                                 const float* __restrict__ bias,
                                                 float* __restrict__ C,
                                                 float* __restrict__ statp,
                                                 int M, int K) {
    __shared__ float As[16][132];
    __shared__ float Bs[16][128];
    __shared__ float redS[16][128];
    __shared__ float redQ[16][128];
    int tid = threadIdx.x;
    int tx = tid & 15;
    int ty = tid >> 4;
    int row0 = blockIdx.x * 128;

    unsigned long long acc[8][4];
#pragma unroll
    for (int r = 0; r < 8; r++)
#pragma unroll
        for (int c = 0; c < 4; c++) acc[r][c] = 0ULL;

    for (int k0 = 0; k0 < K; k0 += 16) {
#pragma unroll
        for (int s = tid; s < 512; s += 256) {
            int r = s >> 2, kq = s & 3;
            int grow = row0 + r, gk = k0 + kq * 4;
            float4 v = make_float4(0.f, 0.f, 0.f, 0.f);
            if (grow < M) {
                const float* arow = A + (size_t)grow * K;
                if (gk + 3 < K) {
                    if (ALIGN4) {
                        v = *(const float4*)&arow[gk];
                    } else {
                        float2 v0 = *(const float2*)&arow[gk];
                        float2 v1 = *(const float2*)&arow[gk + 2];
                        v = make_float4(v0.x, v0.y, v1.x, v1.y);
                    }
                } else {
                    if (gk + 0 < K) v.x = arow[gk + 0];
                    if (gk + 1 < K) v.y = arow[gk + 1];
                    if (gk + 2 < K) v.z = arow[gk + 2];
                    if (gk + 3 < K) v.w = arow[gk + 3];
                }
            }
            As[kq * 4 + 0][r] = v.x;
            As[kq * 4 + 1][r] = v.y;
            As[kq * 4 + 2][r] = v.z;
            As[kq * 4 + 3][r] = v.w;
        }
#pragma unroll
        for (int s = tid; s < 512; s += 256) {
            int kk = s >> 5, nq = s & 31;
            int gk = k0 + kk;
            float4 v = make_float4(0.f, 0.f, 0.f, 0.f);
            if (gk < K) v = *(const float4*)&B[(size_t)gk * 128 + nq * 4];
            *(float4*)&Bs[kk][nq * 4] = v;
        }
        __syncthreads();
#pragma unroll
        for (int kk = 0; kk < 16; kk++) {
            float4 a0 = *(const float4*)&As[kk][ty * 8];
            float4 a1 = *(const float4*)&As[kk][ty * 8 + 4];
            ulonglong2 bA = *(const ulonglong2*)&Bs[kk][tx * 8];
            ulonglong2 bB = *(const ulonglong2*)&Bs[kk][tx * 8 + 4];
            unsigned long long bv[4] = {bA.x, bA.y, bB.x, bB.y};
            float av[8] = {a0.x, a0.y, a0.z, a0.w, a1.x, a1.y, a1.z, a1.w};
#pragma unroll
            for (int r = 0; r < 8; r++) {
                unsigned long long ap;
                unsigned int ai = __float_as_uint(av[r]);
                asm("mov.b64 %0, {%1, %1};" : "=l"(ap) : "r"(ai));
#pragma unroll
                for (int c = 0; c < 4; c++) {
                    asm("fma.rn.f32x2 %0, %1, %2, %3;"
                        : "=l"(acc[r][c]) : "l"(ap), "l"(bv[c]), "l"(acc[r][c]));
                }
            }
        }
        __syncthreads();
    }

    float bv0[8];
#pragma unroll
    for (int c = 0; c < 8; c++) bv0[c] = bias[tx * 8 + c];
    float s8[8], q8[8];
    if (EPI == 2) {
#pragma unroll
        for (int c = 0; c < 8; c++) { s8[c] = 0.f; q8[c] = 0.f; }
    }
#pragma unroll
    for (int r = 0; r < 8; r++) {
        int grow = row0 + ty * 8 + r;
        if (grow < M) {
            float o[8];
#pragma unroll
            for (int c = 0; c < 4; c++) {
                float lo, hi;
                asm("mov.b64 {%0, %1}, %2;" : "=f"(lo), "=f"(hi) : "l"(acc[r][c]));
                o[2 * c] = lo; o[2 * c + 1] = hi;
            }
#pragma unroll
            for (int c = 0; c < 8; c++) {
                float v = o[c] + bv0[c];
                if (EPI == 2) v = tanhf(v);
                if (EPI == 3) v = fmaxf(v, 0.f);
                if (EPI == 2) { s8[c] += v; q8[c] += v * v; }
                o[c] = v;
            }
            *(float4*)&C[(size_t)grow * 128 + tx * 8] = make_float4(o[0], o[1], o[2], o[3]);
            *(float4*)&C[(size_t)grow * 128 + tx * 8 + 4] = make_float4(o[4], o[5], o[6], o[7]);
        }
    }
    if (EPI == 2) {
#pragma unroll
        for (int c = 0; c < 8; c++) { redS[ty][tx * 8 + c] = s8[c]; redQ[ty][tx * 8 + c] = q8[c]; }
        __syncthreads();
        if (tid < 128) {
            float s = 0.f, q = 0.f;
#pragma unroll
            for (int t = 0; t < 16; t++) { s += redS[t][tid]; q += redQ[t][tid]; }
            atomicAdd(&statp[tid], s);
            atomicAdd(&statp[128 + tid], q);
        }
    }
}

// ---------------- parallel fold BN1 into W2: one block per output column ----------------
__global__ void __launch_bounds__(128) k_fold1p(const float* __restrict__ g1,
                                                const float* __restrict__ be1,
                                                const float* __restrict__ W2) {
    __shared__ float red[128];
    int n = blockIdx.x;
    int k = threadIdx.x;
    float mu = g_stat1[k] * (1.0f / NN);
    float var = g_stat1[HF + k] * (1.0f / NN) - mu * mu;
    float sck = g1[k] * rsqrtf(var + BN_EPS);
    float shk = be1[k] - mu * sck;
    float w = W2[k * HF + n];
    g_W2p[k * HF + n] = f2tf(sck * w);
    red[k] = shk * w;
    __syncthreads();
    for (int o = 64; o > 0; o >>= 1) {
        if (k < o) red[k] += red[k + o];
        __syncthreads();
    }
    if (k == 0) g_c2[n] = red[0];
}

// ---------------- fold cell BN into Wc2 (zeroes g_statc) ----------------
__global__ void k_foldc(const float* __restrict__ gc1, const float* __restrict__ bec1,
                        const float* __restrict__ Wc2, const float* __restrict__ bc2) {
    __shared__ float sc[HF], sh[HF];
    int n = threadIdx.x;
    float mu = g_statc[n] * (1.0f / NG);
    float var = g_statc[HF + n] * (1.0f / NG) - mu * mu;
    g_statc[n] = 0.f; g_statc[HF + n] = 0.f;
    float s = gc1[n] * rsqrtf(var + BN_EPS);
    sc[n] = s;
    sh[n] = bec1[n] - mu * s;
    __syncthreads();
    float c = 0.f;
#pragma unroll 8
    for (int k = 0; k < HF; k++) {
        float w = Wc2[k * HF + n];
        g_Wc2p[k * HF + n] = sc[k] * w;
        c += sh[k] * w;
    }
    g_bc2p[n] = bc2[n] + c;
}

// ---------------- final select with BN2 scale computed inline ----------------
__global__ void k_final(const float* __restrict__ g2, const float* __restrict__ be2,
                        float* __restrict__ out) {
    int idx = blockIdx.x * blockDim.x + threadIdx.x;
    if (idx < 2 * HF) g_stat1[idx] = 0.f;   // restore zeros for next replay
    if (idx >= NG * HF) return;
    int k = idx & 127;
    float mu = g_stat2[k] * (1.0f / NN);
    float var = g_stat2[HF + k] * (1.0f / NN) - mu * mu;
    float s = g2[k] * rsqrtf(var + BN_EPS);
    float sh = be2[k] - mu * s;
    float mx = g_smax[idx];
    float r;
    if (mx == neg_inf()) {
        r = neg_inf();
    } else {
        float v = (s >= 0.f) ? mx : g_smin[idx];
        r = s * v + sh;
    }
    out[idx] = r;
}

// ---------------- host ----------------
extern "C" void kernel_launch(void* const* d_in, const int* in_sizes, int n_in,
                              void* d_out, int out_size) {
    const float* drug = (const float*)d_in[0];
    const int* ei = (const int*)d_in[1];
    const int* ib = (const int*)d_in[2];
    const float* gexpr = (const float*)d_in[3];
    const float* W1 = (const float*)d_in[4];
    const float* b1 = (const float*)d_in[5];
    const float* g1 = (const float*)d_in[6];
    const float* be1 = (const float*)d_in[7];
    const float* W2 = (const float*)d_in[8];
    const float* b2 = (const float*)d_in[9];
    const float* g2 = (const float*)d_in[10];
    const float* be2 = (const float*)d_in[11];
    const float* Wc1 = (const float*)d_in[12];
    const float* bc1 = (const float*)d_in[13];
    const float* gc1 = (const float*)d_in[14];
    const float* bec1 = (const float*)d_in[15];
    const float* Wc2 = (const float*)d_in[16];
    const float* bc2 = (const float*)d_in[17];
    float* out = (float*)d_out;

    float *dpp, *hp, *yp, *cellp, *stat1p, *stat2p, *statcp, *W1pp, *W2pp, *c2p, *Wc2pp, *bc2pp;
    __half* x16p;
    cudaGetSymbolAddress((void**)&dpp, g_dp);
    cudaGetSymbolAddress((void**)&hp, g_h);
    cudaGetSymbolAddress((void**)&x16p, g_x16);
    cudaGetSymbolAddress((void**)&yp, g_y);
    cudaGetSymbolAddress((void**)&cellp, g_cell);
    cudaGetSymbolAddress((void**)&stat1p, g_stat1);
    cudaGetSymbolAddress((void**)&stat2p, g_stat2);
    cudaGetSymbolAddress((void**)&statcp, g_statc);
    cudaGetSymbolAddress((void**)&W1pp, g_W1p);
    cudaGetSymbolAddress((void**)&W2pp, g_W2p);
    cudaGetSymbolAddress((void**)&c2p, g_c2);
    cudaGetSymbolAddress((void**)&Wc2pp, g_Wc2p);
    cudaGetSymbolAddress((void**)&bc2pp, g_bc2p);

    const int USMEM = 128 * 129 * 4;
    cudaFuncSetAttribute(gemm_mma<32, 8, 1>, cudaFuncAttributeMaxDynamicSharedMemorySize, USMEM);

    static cudaStream_t sB = nullptr, sC = nullptr;
    static cudaEvent_t eStart = nullptr, e0 = nullptr, eB = nullptr, eC = nullptr,
                       eF = nullptr, eGB = nullptr, eG1 = nullptr;
    if (!sB) {
        cudaStreamCreateWithFlags(&sB, cudaStreamNonBlocking);
        cudaStreamCreateWithFlags(&sC, cudaStreamNonBlocking);
        cudaEventCreateWithFlags(&eStart, cudaEventDisableTiming);
        cudaEventCreateWithFlags(&e0, cudaEventDisableTiming);
        cudaEventCreateWithFlags(&eB, cudaEventDisableTiming);
        cudaEventCreateWithFlags(&eC, cudaEventDisableTiming);
        cudaEventCreateWithFlags(&eF, cudaEventDisableTiming);
        cudaEventCreateWithFlags(&eGB, cudaEventDisableTiming);
        cudaEventCreateWithFlags(&eG1, cudaEventDisableTiming);
    }

    // origin stream: fork anchor
    k_nop<<<1, 32>>>();
    cudaEventRecord(eStart, 0);

    // branch C (forked): pool-accumulator init (+stat2 zero) + cell branch
    cudaStreamWaitEvent(sC, eStart, 0);
    k_ginit<<<(NG * HF + 255) / 256, 256, 0, sC>>>();
    cudaEventRecord(eGB, sC);
    gemm_t<2, false><<<(NG + 127) / 128, 256, 0, sC>>>(gexpr, Wc1, bc1, cellp, statcp, NG, KCELL);
    k_foldc<<<1, HF, 0, sC>>>(gc1, bec1, Wc2, bc2);
    gemm_t<3, true><<<(NG + 127) / 128, 256, 0, sC>>>(cellp, Wc2pp, bc2pp, out + NG * HF, nullptr, NG, HF);
    cudaEventRecord(eC, sC);

    // origin: indegree count
    k_cnt<<<(NE + 255) / 256, 256>>>(ei);
    cudaEventRecord(e0, 0);

    // branch B: CSR build
    cudaStreamWaitEvent(sB, e0, 0);
    k_scan1<<<SCAN_NB, 256, 0, sB>>>();
    k_scan3<<<(NN + 255) / 256, 256, 0, sB>>>();
    k_fill<<<(NE + 255) / 256, 256, 0, sB>>>(ei);
    cudaEventRecord(eB, sB);

    // origin: dinv (fused) + padding
    k_pad<<<(NN * 40 + 255) / 256, 256>>>(drug);
    k_padW<<<(KPAD * HF + 255) / 256, 256>>>(W1);

    // join CSR; layer 1: gather -> gemm1 (relu + bias + stats fused, fp16 out)
    cudaStreamWaitEvent(0, eB, 0);
    k_gather1<<<(NN * 32 + 255) / 256, 256>>>(dpp, hp);
    gemm_mma<20, 5, 0><<<(NN + 127) / 128, 256>>>(hp, W1pp, b1, nullptr, stat1p, x16p, nullptr, NN);
    cudaEventRecord(eG1, 0);

    // stream B: parallel fold1 concurrent with gather2
    cudaStreamWaitEvent(sB, eG1, 0);
    k_fold1p<<<HF, HF, 0, sB>>>(g1, be1, W2);
    cudaEventRecord(eF, sB);

    // layer 2: gather fp16 relu(out1) -> join fold + pool-init -> gemm2 (pool fused)
    k_gather2<<<(NN * 32 + 255) / 256, 256>>>(x16p, yp);
    cudaStreamWaitEvent(0, eF, 0);
    cudaStreamWaitEvent(0, eGB, 0);
    gemm_mma<32, 8, 1><<<(NN + 127) / 128, 256, USMEM>>>(yp, W2pp, b2, c2p, stat2p, nullptr, ib, NN);

    // final select (BN2 fold inline)
    k_final<<<(NG * HF + 255) / 256, 256>>>(g2, be2, out);

    cudaStreamWaitEvent(0, eC, 0);
}

// round 16
// speedup vs baseline: 1.0828x; 1.0318x over previous
#include <cuda_runtime.h>
#include <cuda_fp16.h>
#include <cstdint>

#define NN 200000
#define NE 800000
#define NG 4096
#define KDRUG 78
#define KPAD 80
#define KCELL 954
#define HF 128
#define BN_EPS 1e-5f
#define SCAN_NB 98   // ceil(NN/2048)

// ---------------- scratch (zero-init at load; every run restores zeros) ----------------
__device__ int    g_cnt[NN];
__device__ int    g_fill[NN];
__device__ int    g_off[NN + 1];
__device__ int    g_bsum[SCAN_NB];
__device__ int    g_csr[NE];
__device__ float  g_dinv[NN];
__device__ float  g_t[NN];
__device__ __half g_dp16[(size_t)NN * KPAD];  // drug padded, pre-scaled by dinv_row (fp16)
__device__ float  g_h[(size_t)NN * KPAD];     // agg1 [NN,80] (tf32-rounded)
__device__ float  g_y[(size_t)NN * HF];       // agg2 [NN,128] (tf32-rounded)
__device__ __half g_x16[(size_t)NN * HF];     // relu(out1)*dinv_row (fp16)
__device__ float  g_W1p[KPAD * HF];           // W1 padded [80][128] (tf32-rounded)
__device__ float  g_W2p[HF * HF];             // folded W2 [k][n] (tf32-rounded)
__device__ float  g_stat1[2 * HF];
__device__ float  g_stat2[2 * HF];
__device__ float  g_statc[2 * HF];
__device__ float  g_c2[HF];
__device__ float  g_Wc2p[HF * HF];
__device__ float  g_bc2p[HF];
__device__ float  g_smax[NG * HF];
__device__ float  g_smin[NG * HF];
__device__ float  g_cell[(size_t)NG * HF];

__device__ __forceinline__ float neg_inf() { return __int_as_float(0xff800000); }
__device__ __forceinline__ float pos_inf() { return __int_as_float(0x7f800000); }
__device__ __forceinline__ float f2tf(float f) {
    uint32_t u;
    asm("cvt.rna.tf32.f32 %0, %1;" : "=r"(u) : "f"(f));
    return __uint_as_float(u);
}
__device__ __forceinline__ float4 h4cvt(uint2 u) {
    __half2 h0 = *(__half2*)&u.x;
    __half2 h1 = *(__half2*)&u.y;
    float2 a = __half22float2(h0);
    float2 b = __half22float2(h1);
    return make_float4(a.x, a.y, b.x, b.y);
}

#define CP_A16(saddr, gptr, ssz) \
    asm volatile("cp.async.ca.shared.global [%0], [%1], 16, %2;" :: "r"(saddr), "l"(gptr), "r"(ssz))
#define CP_COMMIT() asm volatile("cp.async.commit_group;" ::: "memory")

// ---------------- tiny no-op kernel (capture fork anchor) ----------------
__global__ void k_nop() {}

// ---------------- edge count (g_cnt arrives zeroed) ----------------
__global__ void k_cnt(const int* __restrict__ ei) {
    int e = blockIdx.x * blockDim.x + threadIdx.x;
    if (e < NE) atomicAdd(&g_cnt[ei[NE + e]], 1);
}

// ---------------- init pool accumulators (-inf / +inf) + zero stat2 ----------------
__global__ void k_ginit() {
    int idx = blockIdx.x * blockDim.x + threadIdx.x;
    if (idx < 2 * HF) g_stat2[idx] = 0.f;   // gemm2 ordered after this via eGB
    if (idx < NG * HF) { g_smax[idx] = neg_inf(); g_smin[idx] = pos_inf(); }
}

// ---------------- CSR scan ----------------
__global__ void __launch_bounds__(256) k_scan1() {
    __shared__ int wsum[8];
    __shared__ int woff[8];
    int t = threadIdx.x;
    int base = blockIdx.x * 2048 + t * 8;
    int v[8];
    int run = 0;
#pragma unroll
    for (int j = 0; j < 8; j++) {
        int idx = base + j;
        int c = (idx < NN) ? g_cnt[idx] : 0;
        v[j] = run;
        run += c;
    }
    int lane = t & 31, w = t >> 5;
    int x = run;
#pragma unroll
    for (int o = 1; o < 32; o <<= 1) {
        int y = __shfl_up_sync(0xffffffffu, x, o);
        if (lane >= o) x += y;
    }
    if (lane == 31) wsum[w] = x;
    __syncthreads();
    if (t == 0) {
        int r = 0;
#pragma unroll
        for (int k = 0; k < 8; k++) { woff[k] = r; r += wsum[k]; }
        g_bsum[blockIdx.x] = r;
    }
    __syncthreads();
    int texc = x - run + woff[w];
#pragma unroll
    for (int j = 0; j < 8; j++) {
        int idx = base + j;
        if (idx < NN) g_off[idx] = texc + v[j];
    }
}

__global__ void __launch_bounds__(256) k_scan3() {
    __shared__ int raw[SCAN_NB];
    __shared__ int pref[SCAN_NB];
    int t = threadIdx.x;
    if (t < SCAN_NB) raw[t] = g_bsum[t];
    __syncthreads();
    if (t == 0) {
        int r = 0;
#pragma unroll 7
        for (int b = 0; b < SCAN_NB; b++) { pref[b] = r; r += raw[b]; }
    }
    __syncthreads();
    int i = blockIdx.x * blockDim.x + t;
    if (i < NN) g_off[i] += pref[i >> 11];
    if (i == 0) g_off[NN] = NE;
}

__global__ void k_fill(const int* __restrict__ ei) {
    int e = blockIdx.x * blockDim.x + threadIdx.x;
    if (e < NE) {
        int d = ei[NE + e];
        int pos = g_off[d] + atomicAdd(&g_fill[d], 1);
        g_csr[pos] = ei[e];
    }
}

// ---------------- pad W1 [78,128] -> [80,128], tf32-rounded ----------------
__global__ void k_padW(const float* __restrict__ W1) {
    int idx = blockIdx.x * blockDim.x + threadIdx.x;
    if (idx >= KPAD * HF) return;
    int row = idx >> 7;
    g_W1p[idx] = (row < KDRUG) ? f2tf(W1[idx]) : 0.f;
}

// ---------------- pad drug: fp16, pre-scaled by dinv_row; also writes g_dinv ----------------
__global__ void k_pad(const float* __restrict__ drug) {
    int idx = blockIdx.x * blockDim.x + threadIdx.x;
    if (idx < NN) g_dinv[idx] = rsqrtf((float)(1 + g_cnt[idx]));
    if (idx >= NN * 40) return;
    int i = idx / 40, s = idx - i * 40;
    float di = rsqrtf((float)(1 + g_cnt[i]));   // recompute (cached cnt load)
    float2 v = make_float2(0.f, 0.f);
    if (s < 39) v = ((const float2*)drug)[(size_t)i * 39 + s];
    ((__half2*)g_dp16)[idx] = __floats2half2_rn(v.x * di, v.y * di);
}

// ---------------- gather1: fp16 pre-scaled source, 80 dims; computes t; cleans cnt/fill ----
__global__ void __launch_bounds__(256) k_gather1(const __half* __restrict__ src,
                                                 float* __restrict__ dst) {
    int gw = (blockIdx.x * 256 + threadIdx.x) >> 5;
    if (gw >= NN) return;
    int lane = threadIdx.x & 31;
    if (lane == 0) { g_cnt[gw] = 0; g_fill[gw] = 0; }
    float di = g_dinv[gw];
    int beg = g_off[gw], end = g_off[gw + 1];
    const uint2* S = (const uint2*)src;   // 20 uint2 per row
    float4 acc = make_float4(0.f, 0.f, 0.f, 0.f);
    if (lane < 20) acc = h4cvt(S[(size_t)gw * 20 + lane]);
    float tacc = di;
    int e = beg;
    for (; e + 3 < end; e += 4) {
        int s0 = g_csr[e], s1 = g_csr[e + 1], s2 = g_csr[e + 2], s3 = g_csr[e + 3];
        tacc += (g_dinv[s0] + g_dinv[s1]) + (g_dinv[s2] + g_dinv[s3]);
        if (lane < 20) {
            float4 v0 = h4cvt(S[(size_t)s0 * 20 + lane]);
            float4 v1 = h4cvt(S[(size_t)s1 * 20 + lane]);
            float4 v2 = h4cvt(S[(size_t)s2 * 20 + lane]);
            float4 v3 = h4cvt(S[(size_t)s3 * 20 + lane]);
            acc.x += (v0.x + v1.x) + (v2.x + v3.x);
            acc.y += (v0.y + v1.y) + (v2.y + v3.y);
            acc.z += (v0.z + v1.z) + (v2.z + v3.z);
            acc.w += (v0.w + v1.w) + (v2.w + v3.w);
        }
    }
    for (; e < end; e++) {
        int s0 = g_csr[e];
        tacc += g_dinv[s0];
        if (lane < 20) {
            float4 v0 = h4cvt(S[(size_t)s0 * 20 + lane]);
            acc.x += v0.x; acc.y += v0.y; acc.z += v0.z; acc.w += v0.w;
        }
    }
    if (lane < 20) {
        acc.x = f2tf(acc.x * di); acc.y = f2tf(acc.y * di);
        acc.z = f2tf(acc.z * di); acc.w = f2tf(acc.w * di);
        ((float4*)dst)[(size_t)gw * 20 + lane] = acc;
    }
    if (lane == 0) g_t[gw] = tacc;
}

// ---------------- gather2: fp16 pre-scaled source, 128 dims; no dinv loads ----------------
__global__ void __launch_bounds__(256) k_gather2(const __half* __restrict__ src,
                                                 float* __restrict__ dst) {
    int gw = (blockIdx.x * 256 + threadIdx.x) >> 5;
    if (gw >= NN) return;
    int lane = threadIdx.x & 31;
    float di = g_dinv[gw];
    int beg = g_off[gw], end = g_off[gw + 1];
    const uint2* S = (const uint2*)src;   // 32 uint2 per row
    float4 acc = h4cvt(S[(size_t)gw * 32 + lane]);
    int e = beg;
    for (; e + 3 < end; e += 4) {
        int s0 = g_csr[e], s1 = g_csr[e + 1], s2 = g_csr[e + 2], s3 = g_csr[e + 3];
        float4 v0 = h4cvt(S[(size_t)s0 * 32 + lane]);
        float4 v1 = h4cvt(S[(size_t)s1 * 32 + lane]);
        float4 v2 = h4cvt(S[(size_t)s2 * 32 + lane]);
        float4 v3 = h4cvt(S[(size_t)s3 * 32 + lane]);
        acc.x += (v0.x + v1.x) + (v2.x + v3.x);
        acc.y += (v0.y + v1.y) + (v2.y + v3.y);
        acc.z += (v0.z + v1.z) + (v2.z + v3.z);
        acc.w += (v0.w + v1.w) + (v2.w + v3.w);
    }
    for (; e < end; e++) {
        int s0 = g_csr[e];
        float4 v0 = h4cvt(S[(size_t)s0 * 32 + lane]);
        acc.x += v0.x; acc.y += v0.y; acc.z += v0.z; acc.w += v0.w;
    }
    acc.x = f2tf(acc.x * di); acc.y = f2tf(acc.y * di);
    acc.z = f2tf(acc.z * di); acc.w = f2tf(acc.w * di);
    ((float4*)dst)[(size_t)gw * 32 + lane] = acc;
}

// ---------------- tf32 mma.sync GEMM, cp.async double buffered ----------------
// EPI 0: relu(+bias), store fp16 (v * dinv_row), fused BN stats (unscaled) -> statp
// EPI 1: v = acc + bias + (dinv*t)*cvec; u = relu(v); NO gmem matrix write.
//        Fused pool via smem staging + per-graph-segment atomics; BN2 stats -> statp.
template <int KF4, int KTILES, int EPI>
__global__ void __launch_bounds__(256) gemm_mma(const float* __restrict__ A,
                                                const float* __restrict__ B,
                                                const float* __restrict__ bias,
                                                const float* __restrict__ cvec,
                                                float* __restrict__ statp,
                                                __half* __restrict__ C16,
                                                const int* __restrict__ ib, int M) {
    extern __shared__ float Udyn[];     // EPI1 only: [128][129] staged relu(out2)
    __shared__ float As[2][128][20];
    __shared__ float Bs[2][16][136];
    __shared__ float sS[4][128];
    __shared__ float sQ[4][128];
    __shared__ int   sib[128];
    int tid = threadIdx.x, lane = tid & 31, wid = tid >> 5;
    int gid = lane >> 2, tig = lane & 3;
    int wm = wid & 3, wn = wid >> 2;
    int rbase = wm * 32, cbase = wn * 64;
    int row0 = blockIdx.x << 7;

    float cacc[2][8][4];
#pragma unroll
    for (int mi = 0; mi < 2; mi++)
#pragma unroll
        for (int ni = 0; ni < 8; ni++)
#pragma unroll
            for (int q = 0; q < 4; q++) cacc[mi][ni][q] = 0.f;

    int ar[2], akq[2], bk[2], bnq[2];
    uint32_t aaddr[2][2], baddr[2][2];
#pragma unroll
    for (int i = 0; i < 2; i++) {
        int idx = tid + i * 256;
        ar[i] = idx >> 2; akq[i] = idx & 3;
        bk[i] = idx >> 5; bnq[i] = idx & 31;
#pragma unroll
        for (int b = 0; b < 2; b++) {
            aaddr[b][i] = (uint32_t)__cvta_generic_to_shared(&As[b][ar[i]][akq[i] * 4]);
            baddr[b][i] = (uint32_t)__cvta_generic_to_shared(&Bs[b][bk[i]][bnq[i] * 4]);
        }
    }

    auto load_chunk = [&](int kc, int buf) {
#pragma unroll
        for (int i = 0; i < 2; i++) {
            int grow = row0 + ar[i];
            const float4* src = (const float4*)A +
                ((grow < M ? (size_t)grow : 0) * KF4 + kc * 4 + akq[i]);
            uint32_t ssz = (grow < M) ? 16u : 0u;
            CP_A16(aaddr[buf][i], src, ssz);
        }
#pragma unroll
        for (int i = 0; i < 2; i++) {
            const float4* src = (const float4*)B + ((size_t)(kc * 16 + bk[i]) * 32 + bnq[i]);
            CP_A16(baddr[buf][i], src, 16u);
        }
    };

    load_chunk(0, 0);
    CP_COMMIT();

    for (int kc = 0; kc < KTILES; kc++) {
        if (kc + 1 < KTILES) {
            load_chunk(kc + 1, (kc + 1) & 1);
            CP_COMMIT();
            asm volatile("cp.async.wait_group 1;" ::: "memory");
        } else {
            asm volatile("cp.async.wait_group 0;" ::: "memory");
        }
        __syncthreads();
        int buf = kc & 1;
#pragma unroll
        for (int ks = 0; ks < 2; ks++) {
            uint32_t af[2][4];
#pragma unroll
            for (int mi = 0; mi < 2; mi++) {
                int rr = rbase + mi * 16 + gid;
                af[mi][0] = __float_as_uint(As[buf][rr][ks * 8 + tig]);
                af[mi][1] = __float_as_uint(As[buf][rr + 8][ks * 8 + tig]);
                af[mi][2] = __float_as_uint(As[buf][rr][ks * 8 + tig + 4]);
                af[mi][3] = __float_as_uint(As[buf][rr + 8][ks * 8 + tig + 4]);
            }
            uint32_t bf[8][2];
#pragma unroll
            for (int ni = 0; ni < 8; ni++) {
                int nn = cbase + ni * 8 + gid;
                bf[ni][0] = __float_as_uint(Bs[buf][ks * 8 + tig][nn]);
                bf[ni][1] = __float_as_uint(Bs[buf][ks * 8 + tig + 4][nn]);
            }
#pragma unroll
            for (int mi = 0; mi < 2; mi++)
#pragma unroll
                for (int ni = 0; ni < 8; ni++) {
                    asm volatile(
                        "mma.sync.aligned.m16n8k8.row.col.f32.tf32.tf32.f32 "
                        "{%0,%1,%2,%3}, {%4,%5,%6,%7}, {%8,%9}, {%0,%1,%2,%3};"
                        : "+f"(cacc[mi][ni][0]), "+f"(cacc[mi][ni][1]),
                          "+f"(cacc[mi][ni][2]), "+f"(cacc[mi][ni][3])
                        : "r"(af[mi][0]), "r"(af[mi][1]), "r"(af[mi][2]), "r"(af[mi][3]),
                          "r"(bf[ni][0]), "r"(bf[ni][1]));
                }
        }
        __syncthreads();
    }

    float bs[8][2], cvv[8][2];
#pragma unroll
    for (int ni = 0; ni < 8; ni++) {
        int col = cbase + ni * 8 + tig * 2;
        bs[ni][0] = bias[col];
        bs[ni][1] = bias[col + 1];
        if (EPI == 1) { cvv[ni][0] = cvec[col]; cvv[ni][1] = cvec[col + 1]; }
    }

    if (EPI == 0) {
        float sacc[8][2], qacc[8][2];
#pragma unroll
        for (int ni = 0; ni < 8; ni++) {
            sacc[ni][0] = 0.f; sacc[ni][1] = 0.f;
            qacc[ni][0] = 0.f; qacc[ni][1] = 0.f;
        }
#pragma unroll
        for (int mi = 0; mi < 2; mi++) {
            int rA = row0 + rbase + mi * 16 + gid;
            int rB = rA + 8;
            float dA = (rA < M) ? g_dinv[rA] : 0.f;
            float dB = (rB < M) ? g_dinv[rB] : 0.f;
#pragma unroll
            for (int ni = 0; ni < 8; ni++) {
                int col = cbase + ni * 8 + tig * 2;
                float v0 = fmaxf(cacc[mi][ni][0] + bs[ni][0], 0.f);
                float v1 = fmaxf(cacc[mi][ni][1] + bs[ni][1], 0.f);
                float v2 = fmaxf(cacc[mi][ni][2] + bs[ni][0], 0.f);
                float v3 = fmaxf(cacc[mi][ni][3] + bs[ni][1], 0.f);
                if (rA < M) {
                    sacc[ni][0] += v0; qacc[ni][0] += v0 * v0;
                    sacc[ni][1] += v1; qacc[ni][1] += v1 * v1;
                    ((__half2*)C16)[(size_t)rA * 64 + (col >> 1)] =
                        __floats2half2_rn(v0 * dA, v1 * dA);
                }
                if (rB < M) {
                    sacc[ni][0] += v2; qacc[ni][0] += v2 * v2;
                    sacc[ni][1] += v3; qacc[ni][1] += v3 * v3;
                    ((__half2*)C16)[(size_t)rB * 64 + (col >> 1)] =
                        __floats2half2_rn(v2 * dB, v3 * dB);
                }
            }
        }
#pragma unroll
        for (int ni = 0; ni < 8; ni++)
#pragma unroll
            for (int j = 0; j < 2; j++) {
#pragma unroll
                for (int off = 4; off < 32; off <<= 1) {
                    sacc[ni][j] += __shfl_xor_sync(0xffffffffu, sacc[ni][j], off);
                    qacc[ni][j] += __shfl_xor_sync(0xffffffffu, qacc[ni][j], off);
                }
            }
        if (gid == 0) {
#pragma unroll
            for (int ni = 0; ni < 8; ni++) {
                int col = cbase + ni * 8 + tig * 2;
                sS[wm][col] = sacc[ni][0]; sS[wm][col + 1] = sacc[ni][1];
                sQ[wm][col] = qacc[ni][0]; sQ[wm][col + 1] = qacc[ni][1];
            }
        }
        __syncthreads();
        if (tid < 128) {
            float s = 0.f, q = 0.f;
#pragma unroll
            for (int w = 0; w < 4; w++) { s += sS[w][tid]; q += sQ[w][tid]; }
            atomicAdd(&statp[tid], s);
            atomicAdd(&statp[128 + tid], q);
        }
    } else {
        // EPI 1: stage relu(out2) to smem, then per-graph pooled reduction
#pragma unroll
        for (int mi = 0; mi < 2; mi++) {
            int lrA = rbase + mi * 16 + gid;
            int rA = row0 + lrA, rB = rA + 8;
            float sA = (rA < M) ? g_dinv[rA] * g_t[rA] : 0.f;
            float sB = (rB < M) ? g_dinv[rB] * g_t[rB] : 0.f;
#pragma unroll
            for (int ni = 0; ni < 8; ni++) {
                int col = cbase + ni * 8 + tig * 2;
                float v0 = fmaxf(cacc[mi][ni][0] + bs[ni][0] + sA * cvv[ni][0], 0.f);
                float v1 = fmaxf(cacc[mi][ni][1] + bs[ni][1] + sA * cvv[ni][1], 0.f);
                float v2 = fmaxf(cacc[mi][ni][2] + bs[ni][0] + sB * cvv[ni][0], 0.f);
                float v3 = fmaxf(cacc[mi][ni][3] + bs[ni][1] + sB * cvv[ni][1], 0.f);
                Udyn[lrA * 129 + col] = v0;
                Udyn[lrA * 129 + col + 1] = v1;
                Udyn[(lrA + 8) * 129 + col] = v2;
                Udyn[(lrA + 8) * 129 + col + 1] = v3;
            }
        }
        if (tid < 128) {
            int grow = row0 + tid;
            sib[tid] = (grow < M) ? ib[grow] : -1;
        }
        __syncthreads();
        int col = tid & 127, half = tid >> 7;
        int r0 = half * 64, r1 = r0 + 64;
        float s = 0.f, q = 0.f, mx = 0.f, mn = 0.f;
        int gcur = -1;
        for (int r = r0; r < r1; r++) {
            int g = sib[r];
            if (g < 0) break;   // trailing invalid rows only
            float u = Udyn[r * 129 + col];
            s += u; q += u * u;
            if (g != gcur) {
                if (gcur >= 0) {
                    atomicMax((int*)&g_smax[gcur * HF + col], __float_as_int(mx));
                    atomicMin((int*)&g_smin[gcur * HF + col], __float_as_int(mn));
                }
                gcur = g; mx = u; mn = u;
            } else {
                mx = fmaxf(mx, u); mn = fminf(mn, u);
            }
        }
        if (gcur >= 0) {
            atomicMax((int*)&g_smax[gcur * HF + col], __float_as_int(mx));
            atomicMin((int*)&g_smin[gcur * HF + col], __float_as_int(mn));
        }
        atomicAdd(&statp[col], s);
        atomicAdd(&statp[HF + col], q);
    }
}

// ---------------- FFMA2 GEMM (cell branch only) ----------------
template <int EPI, bool ALIGN4>
__global__ void __launch_bounds__(256, 2) gemm_t(const float* __restrict__ A,
                                                 const float* __restrict__ B,
                                                 const float* __restrict__ bias,
                                                 float* __restrict__ C,
                                                 float* __restrict__ statp,
                                                 int M, int K) {
    __shared__ float As[16][132];
    __shared__ float Bs[16][128];
    __shared__ float redS[16][128];
    __shared__ float redQ[16][128];
    int tid = threadIdx.x;
    int tx = tid & 15;
    int ty = tid >> 4;
    int row0 = blockIdx.x * 128;

    unsigned long long acc[8][4];
#pragma unroll
    for (int r = 0; r < 8; r++)
#pragma unroll
        for (int c = 0; c < 4; c++) acc[r][c] = 0ULL;

    for (int k0 = 0; k0 < K; k0 += 16) {
#pragma unroll
        for (int s = tid; s < 512; s += 256) {
            int r = s >> 2, kq = s & 3;
            int grow = row0 + r, gk = k0 + kq * 4;
            float4 v = make_float4(0.f, 0.f, 0.f, 0.f);
            if (grow < M) {
                const float* arow = A + (size_t)grow * K;
                if (gk + 3 < K) {
                    if (ALIGN4) {
                        v = *(const float4*)&arow[gk];
                    } else {
                        float2 v0 = *(const float2*)&arow[gk];
                        float2 v1 = *(const float2*)&arow[gk + 2];
                        v = make_float4(v0.x, v0.y, v1.x, v1.y);
                    }
                } else {
                    if (gk + 0 < K) v.x = arow[gk + 0];
                    if (gk + 1 < K) v.y = arow[gk + 1];
                    if (gk + 2 < K) v.z = arow[gk + 2];
                    if (gk + 3 < K) v.w = arow[gk + 3];
                }
            }
            As[kq * 4 + 0][r] = v.x;
            As[kq * 4 + 1][r] = v.y;
            As[kq * 4 + 2][r] = v.z;
            As[kq * 4 + 3][r] = v.w;
        }
#pragma unroll
        for (int s = tid; s < 512; s += 256) {
            int kk = s >> 5, nq = s & 31;
            int gk = k0 + kk;
            float4 v = make_float4(0.f, 0.f, 0.f, 0.f);
            if (gk < K) v = *(const float4*)&B[(size_t)gk * 128 + nq * 4];
            *(float4*)&Bs[kk][nq * 4] = v;
        }
        __syncthreads();
#pragma unroll
        for (int kk = 0; kk < 16; kk++) {
            float4 a0 = *(const float4*)&As[kk][ty * 8];
            float4 a1 = *(const float4*)&As[kk][ty * 8 + 4];
            ulonglong2 bA = *(const ulonglong2*)&Bs[kk][tx * 8];
            ulonglong2 bB = *(const ulonglong2*)&Bs[kk][tx * 8 + 4];
            unsigned long long bv[4] = {bA.x, bA.y, bB.x, bB.y};
            float av[8] = {a0.x, a0.y, a0.z, a0.w, a1.x, a1.y, a1.z, a1.w};
#pragma unroll
            for (int r = 0; r < 8; r++) {
                unsigned long long ap;
                unsigned int ai = __float_as_uint(av[r]);
                asm("mov.b64 %0, {%1, %1};" : "=l"(ap) : "r"(ai));
#pragma unroll
                for (int c = 0; c < 4; c++) {
                    asm("fma.rn.f32x2 %0, %1, %2, %3;"
                        : "=l"(acc[r][c]) : "l"(ap), "l"(bv[c]), "l"(acc[r][c]));
                }
            }
        }
        __syncthreads();
    }

    float bv0[8];
#pragma unroll
    for (int c = 0; c < 8; c++) bv0[c] = bias[tx * 8 + c];
    float s8[8], q8[8];
    if (EPI == 2) {
#pragma unroll
        for (int c = 0; c < 8; c++) { s8[c] = 0.f; q8[c] = 0.f; }
    }
#pragma unroll
    for (int r = 0; r < 8; r++) {
        int grow = row0 + ty * 8 + r;
        if (grow < M) {
            float o[8];
#pragma unroll
            for (int c = 0; c < 4; c++) {
                float lo, hi;
                asm("mov.b64 {%0, %1}, %2;" : "=f"(lo), "=f"(hi) : "l"(acc[r][c]));
                o[2 * c] = lo; o[2 * c + 1] = hi;
            }
#pragma unroll
            for (int c = 0; c < 8; c++) {
                float v = o[c] + bv0[c];
                if (EPI == 2) v = tanhf(v);
                if (EPI == 3) v = fmaxf(v, 0.f);
                if (EPI == 2) { s8[c] += v; q8[c] += v * v; }
                o[c] = v;
            }
            *(float4*)&C[(size_t)grow * 128 + tx * 8] = make_float4(o[0], o[1], o[2], o[3]);
            *(float4*)&C[(size_t)grow * 128 + tx * 8 + 4] = make_float4(o[4], o[5], o[6], o[7]);
        }
    }
    if (EPI == 2) {
#pragma unroll
        for (int c = 0; c < 8; c++) { redS[ty][tx * 8 + c] = s8[c]; redQ[ty][tx * 8 + c] = q8[c]; }
        __syncthreads();
        if (tid < 128) {
            float s = 0.f, q = 0.f;
#pragma unroll
            for (int t = 0; t < 16; t++) { s += redS[t][tid]; q += redQ[t][tid]; }
            atomicAdd(&statp[tid], s);
            atomicAdd(&statp[128 + tid], q);
        }
    }
}

// ---------------- parallel fold BN1 into W2: one block per output column ----------------
__global__ void __launch_bounds__(128) k_fold1p(const float* __restrict__ g1,
                                                const float* __restrict__ be1,
                                                const float* __restrict__ W2) {
    __shared__ float red[128];
    int n = blockIdx.x;
    int k = threadIdx.x;
    float mu = g_stat1[k] * (1.0f / NN);
    float var = g_stat1[HF + k] * (1.0f / NN) - mu * mu;
    float sck = g1[k] * rsqrtf(var + BN_EPS);
    float shk = be1[k] - mu * sck;
    float w = W2[k * HF + n];
    g_W2p[k * HF + n] = f2tf(sck * w);
    red[k] = shk * w;
    __syncthreads();
    for (int o = 64; o > 0; o >>= 1) {
        if (k < o) red[k] += red[k + o];
        __syncthreads();
    }
    if (k == 0) g_c2[n] = red[0];
}

// ---------------- fold cell BN into Wc2 (zeroes g_statc) ----------------
__global__ void k_foldc(const float* __restrict__ gc1, const float* __restrict__ bec1,
                        const float* __restrict__ Wc2, const float* __restrict__ bc2) {
    __shared__ float sc[HF], sh[HF];
    int n = threadIdx.x;
    float mu = g_statc[n] * (1.0f / NG);
    float var = g_statc[HF + n] * (1.0f / NG) - mu * mu;
    g_statc[n] = 0.f; g_statc[HF + n] = 0.f;
    float s = gc1[n] * rsqrtf(var + BN_EPS);
    sc[n] = s;
    sh[n] = bec1[n] - mu * s;
    __syncthreads();
    float c = 0.f;
#pragma unroll 8
    for (int k = 0; k < HF; k++) {
        float w = Wc2[k * HF + n];
        g_Wc2p[k * HF + n] = sc[k] * w;
        c += sh[k] * w;
    }
    g_bc2p[n] = bc2[n] + c;
}

// ---------------- final select with BN2 scale computed inline ----------------
__global__ void k_final(const float* __restrict__ g2, const float* __restrict__ be2,
                        float* __restrict__ out) {
    int idx = blockIdx.x * blockDim.x + threadIdx.x;
    if (idx < 2 * HF) g_stat1[idx] = 0.f;   // restore zeros for next replay
    if (idx >= NG * HF) return;
    int k = idx & 127;
    float mu = g_stat2[k] * (1.0f / NN);
    float var = g_stat2[HF + k] * (1.0f / NN) - mu * mu;
    float s = g2[k] * rsqrtf(var + BN_EPS);
    float sh = be2[k] - mu * s;
    float mx = g_smax[idx];
    float r;
    if (mx == neg_inf()) {
        r = neg_inf();
    } else {
        float v = (s >= 0.f) ? mx : g_smin[idx];
        r = s * v + sh;
    }
    out[idx] = r;
}

// ---------------- host ----------------
extern "C" void kernel_launch(void* const* d_in, const int* in_sizes, int n_in,
                              void* d_out, int out_size) {
    const float* drug = (const float*)d_in[0];
    const int* ei = (const int*)d_in[1];
    const int* ib = (const int*)d_in[2];
    const float* gexpr = (const float*)d_in[3];
    const float* W1 = (const float*)d_in[4];
    const float* b1 = (const float*)d_in[5];
    const float* g1 = (const float*)d_in[6];
    const float* be1 = (const float*)d_in[7];
    const float* W2 = (const float*)d_in[8];
    const float* b2 = (const float*)d_in[9];
    const float* g2 = (const float*)d_in[10];
    const float* be2 = (const float*)d_in[11];
    const float* Wc1 = (const float*)d_in[12];
    const float* bc1 = (const float*)d_in[13];
    const float* gc1 = (const float*)d_in[14];
    const float* bec1 = (const float*)d_in[15];
    const float* Wc2 = (const float*)d_in[16];
    const float* bc2 = (const float*)d_in[17];
    float* out = (float*)d_out;

    float *hp, *yp, *cellp, *stat1p, *stat2p, *statcp, *W1pp, *W2pp, *c2p, *Wc2pp, *bc2pp;
    __half *x16p, *dp16p;
    cudaGetSymbolAddress((void**)&dp16p, g_dp16);
    cudaGetSymbolAddress((void**)&hp, g_h);
    cudaGetSymbolAddress((void**)&x16p, g_x16);
    cudaGetSymbolAddress((void**)&yp, g_y);
    cudaGetSymbolAddress((void**)&cellp, g_cell);
    cudaGetSymbolAddress((void**)&stat1p, g_stat1);
    cudaGetSymbolAddress((void**)&stat2p, g_stat2);
    cudaGetSymbolAddress((void**)&statcp, g_statc);
    cudaGetSymbolAddress((void**)&W1pp, g_W1p);
    cudaGetSymbolAddress((void**)&W2pp, g_W2p);
    cudaGetSymbolAddress((void**)&c2p, g_c2);
    cudaGetSymbolAddress((void**)&Wc2pp, g_Wc2p);
    cudaGetSymbolAddress((void**)&bc2pp, g_bc2p);

    const int USMEM = 128 * 129 * 4;
    cudaFuncSetAttribute(gemm_mma<32, 8, 1>, cudaFuncAttributeMaxDynamicSharedMemorySize, USMEM);

    static cudaStream_t sB = nullptr, sC = nullptr;
    static cudaEvent_t eStart = nullptr, e0 = nullptr, eB = nullptr, eC = nullptr,
                       eF = nullptr, eGB = nullptr, eG1 = nullptr;
    if (!sB) {
        cudaStreamCreateWithFlags(&sB, cudaStreamNonBlocking);
        cudaStreamCreateWithFlags(&sC, cudaStreamNonBlocking);
        cudaEventCreateWithFlags(&eStart, cudaEventDisableTiming);
        cudaEventCreateWithFlags(&e0, cudaEventDisableTiming);
        cudaEventCreateWithFlags(&eB, cudaEventDisableTiming);
        cudaEventCreateWithFlags(&eC, cudaEventDisableTiming);
        cudaEventCreateWithFlags(&eF, cudaEventDisableTiming);
        cudaEventCreateWithFlags(&eGB, cudaEventDisableTiming);
        cudaEventCreateWithFlags(&eG1, cudaEventDisableTiming);
    }

    // origin stream: fork anchor
    k_nop<<<1, 32>>>();
    cudaEventRecord(eStart, 0);

    // branch C (forked): pool-accumulator init (+stat2 zero) + cell branch
    cudaStreamWaitEvent(sC, eStart, 0);
    k_ginit<<<(NG * HF + 255) / 256, 256, 0, sC>>>();
    cudaEventRecord(eGB, sC);
    gemm_t<2, false><<<(NG + 127) / 128, 256, 0, sC>>>(gexpr, Wc1, bc1, cellp, statcp, NG, KCELL);
    k_foldc<<<1, HF, 0, sC>>>(gc1, bec1, Wc2, bc2);
    gemm_t<3, true><<<(NG + 127) / 128, 256, 0, sC>>>(cellp, Wc2pp, bc2pp, out + NG * HF, nullptr, NG, HF);
    cudaEventRecord(eC, sC);

    // origin: indegree count
    k_cnt<<<(NE + 255) / 256, 256>>>(ei);
    cudaEventRecord(e0, 0);

    // branch B: CSR build
    cudaStreamWaitEvent(sB, e0, 0);
    k_scan1<<<SCAN_NB, 256, 0, sB>>>();
    k_scan3<<<(NN + 255) / 256, 256, 0, sB>>>();
    k_fill<<<(NE + 255) / 256, 256, 0, sB>>>(ei);
    cudaEventRecord(eB, sB);

    // origin: dinv + fp16 pre-scaled drug padding
    k_pad<<<(NN * 40 + 255) / 256, 256>>>(drug);
    k_padW<<<(KPAD * HF + 255) / 256, 256>>>(W1);

    // join CSR; layer 1: gather (fp16 src) -> gemm1 (relu + bias + stats fused, fp16*dinv out)
    cudaStreamWaitEvent(0, eB, 0);
    k_gather1<<<(NN * 32 + 255) / 256, 256>>>(dp16p, hp);
    gemm_mma<20, 5, 0><<<(NN + 127) / 128, 256>>>(hp, W1pp, b1, nullptr, stat1p, x16p, nullptr, NN);
    cudaEventRecord(eG1, 0);

    // stream B: parallel fold1 concurrent with gather2
    cudaStreamWaitEvent(sB, eG1, 0);
    k_fold1p<<<HF, HF, 0, sB>>>(g1, be1, W2);
    cudaEventRecord(eF, sB);

    // layer 2: gather fp16 pre-scaled -> join fold + pool-init -> gemm2 (pool fused)
    k_gather2<<<(NN * 32 + 255) / 256, 256>>>(x16p, yp);
    cudaStreamWaitEvent(0, eF, 0);
    cudaStreamWaitEvent(0, eGB, 0);
    gemm_mma<32, 8, 1><<<(NN + 127) / 128, 256, USMEM>>>(yp, W2pp, b2, c2p, stat2p, nullptr, ib, NN);

    // final select (BN2 fold inline)
    k_final<<<(NG * HF + 255) / 256, 256>>>(g2, be2, out);

    cudaStreamWaitEvent(0, eC, 0);
}

// round 17
// speedup vs baseline: 1.1748x; 1.0850x over previous
#include <cuda_runtime.h>
#include <cuda_fp16.h>
#include <cstdint>

#define NN 200000
#define NE 800000
#define NG 4096
#define KDRUG 78
#define KPAD 80
#define KCELL 954
#define HF 128
#define BN_EPS 1e-5f
#define SCAN_NB 98   // ceil(NN/2048)

// ---------------- scratch (zero-init at load; every run restores zeros) ----------------
__device__ int    g_cnt[NN];
__device__ int    g_fill[NN];
__device__ int    g_off[NN + 1];
__device__ int    g_bsum[SCAN_NB];
__device__ int    g_csr[NE];
__device__ float  g_dinv[NN];
__device__ float  g_t[NN];
__device__ __half g_dp16[(size_t)NN * KPAD];  // drug padded, pre-scaled by dinv_row (fp16)
__device__ __half g_h16[(size_t)NN * KPAD];   // agg1 [NN,80] fp16
__device__ __half g_y16[(size_t)NN * HF];     // agg2 [NN,128] fp16
__device__ __half g_x16[(size_t)NN * HF];     // relu(out1)*dinv_row (fp16)
__device__ __half g_W1h[HF * KPAD];           // W1 transposed [n=128][k=80] fp16
__device__ __half g_W2h[HF * HF];             // folded W2 transposed [n][k] fp16
__device__ float  g_stat1[2 * HF];
__device__ float  g_stat2[2 * HF];
__device__ float  g_statc[2 * HF];
__device__ float  g_c2[HF];
__device__ float  g_Wc2p[HF * HF];
__device__ float  g_bc2p[HF];
__device__ float  g_smax[NG * HF];
__device__ float  g_smin[NG * HF];
__device__ float  g_cell[(size_t)NG * HF];

__device__ __forceinline__ float neg_inf() { return __int_as_float(0xff800000); }
__device__ __forceinline__ float pos_inf() { return __int_as_float(0x7f800000); }
__device__ __forceinline__ float4 h4cvt(uint2 u) {
    __half2 h0 = *(__half2*)&u.x;
    __half2 h1 = *(__half2*)&u.y;
    float2 a = __half22float2(h0);
    float2 b = __half22float2(h1);
    return make_float4(a.x, a.y, b.x, b.y);
}
__device__ __forceinline__ uint2 h4pack(float4 v) {
    uint2 r;
    __half2 h0 = __floats2half2_rn(v.x, v.y);
    __half2 h1 = __floats2half2_rn(v.z, v.w);
    r.x = *(uint32_t*)&h0;
    r.y = *(uint32_t*)&h1;
    return r;
}

#define CP_A16(saddr, gptr, ssz) \
    asm volatile("cp.async.ca.shared.global [%0], [%1], 16, %2;" :: "r"(saddr), "l"(gptr), "r"(ssz))
#define CP_COMMIT() asm volatile("cp.async.commit_group;" ::: "memory")

// ---------------- tiny no-op kernel (capture fork anchor) ----------------
__global__ void k_nop() {}

// ---------------- edge count (g_cnt arrives zeroed) ----------------
__global__ void k_cnt(const int* __restrict__ ei) {
    int e = blockIdx.x * blockDim.x + threadIdx.x;
    if (e < NE) atomicAdd(&g_cnt[ei[NE + e]], 1);
}

// ---------------- init pool accumulators (-inf / +inf) + zero stat2 ----------------
__global__ void k_ginit() {
    int idx = blockIdx.x * blockDim.x + threadIdx.x;
    if (idx < 2 * HF) g_stat2[idx] = 0.f;
    if (idx < NG * HF) { g_smax[idx] = neg_inf(); g_smin[idx] = pos_inf(); }
}

// ---------------- CSR scan ----------------
__global__ void __launch_bounds__(256) k_scan1() {
    __shared__ int wsum[8];
    __shared__ int woff[8];
    int t = threadIdx.x;
    int base = blockIdx.x * 2048 + t * 8;
    int v[8];
    int run = 0;
#pragma unroll
    for (int j = 0; j < 8; j++) {
        int idx = base + j;
        int c = (idx < NN) ? g_cnt[idx] : 0;
        v[j] = run;
        run += c;
    }
    int lane = t & 31, w = t >> 5;
    int x = run;
#pragma unroll
    for (int o = 1; o < 32; o <<= 1) {
        int y = __shfl_up_sync(0xffffffffu, x, o);
        if (lane >= o) x += y;
    }
    if (lane == 31) wsum[w] = x;
    __syncthreads();
    if (t == 0) {
        int r = 0;
#pragma unroll
        for (int k = 0; k < 8; k++) { woff[k] = r; r += wsum[k]; }
        g_bsum[blockIdx.x] = r;
    }
    __syncthreads();
    int texc = x - run + woff[w];
#pragma unroll
    for (int j = 0; j < 8; j++) {
        int idx = base + j;
        if (idx < NN) g_off[idx] = texc + v[j];
    }
}

__global__ void __launch_bounds__(256) k_scan3() {
    __shared__ int raw[SCAN_NB];
    __shared__ int pref[SCAN_NB];
    int t = threadIdx.x;
    if (t < SCAN_NB) raw[t] = g_bsum[t];
    __syncthreads();
    if (t == 0) {
        int r = 0;
#pragma unroll 7
        for (int b = 0; b < SCAN_NB; b++) { pref[b] = r; r += raw[b]; }
    }
    __syncthreads();
    int i = blockIdx.x * blockDim.x + t;
    if (i < NN) g_off[i] += pref[i >> 11];
    if (i == 0) g_off[NN] = NE;
}

__global__ void k_fill(const int* __restrict__ ei) {
    int e = blockIdx.x * blockDim.x + threadIdx.x;
    if (e < NE) {
        int d = ei[NE + e];
        int pos = g_off[d] + atomicAdd(&g_fill[d], 1);
        g_csr[pos] = ei[e];
    }
}

// ---------------- pad+transpose W1 -> [n=128][k=80] fp16 ----------------
__global__ void k_padW(const float* __restrict__ W1) {
    int idx = blockIdx.x * blockDim.x + threadIdx.x;
    if (idx >= HF * KPAD) return;
    int n = idx / KPAD, k = idx - n * KPAD;
    float w = (k < KDRUG) ? W1[k * HF + n] : 0.f;
    g_W1h[idx] = __float2half_rn(w);
}

// ---------------- pad drug: fp16, pre-scaled by dinv_row; also writes g_dinv ----------------
__global__ void k_pad(const float* __restrict__ drug) {
    int idx = blockIdx.x * blockDim.x + threadIdx.x;
    if (idx < NN) g_dinv[idx] = rsqrtf((float)(1 + g_cnt[idx]));
    if (idx >= NN * 40) return;
    int i = idx / 40, s = idx - i * 40;
    float di = rsqrtf((float)(1 + g_cnt[i]));
    float2 v = make_float2(0.f, 0.f);
    if (s < 39) v = ((const float2*)drug)[(size_t)i * 39 + s];
    ((__half2*)g_dp16)[idx] = __floats2half2_rn(v.x * di, v.y * di);
}

// ---------------- gather1: fp16 src, 80 dims; computes t; fp16 dst; cleans cnt/fill ----
__global__ void __launch_bounds__(256) k_gather1(const __half* __restrict__ src,
                                                 __half* __restrict__ dst) {
    int gw = (blockIdx.x * 256 + threadIdx.x) >> 5;
    if (gw >= NN) return;
    int lane = threadIdx.x & 31;
    if (lane == 0) { g_cnt[gw] = 0; g_fill[gw] = 0; }
    float di = g_dinv[gw];
    int beg = g_off[gw], end = g_off[gw + 1];
    const uint2* S = (const uint2*)src;   // 20 uint2 per row
    float4 acc = make_float4(0.f, 0.f, 0.f, 0.f);
    if (lane < 20) acc = h4cvt(S[(size_t)gw * 20 + lane]);
    float tacc = di;
    int e = beg;
    for (; e + 3 < end; e += 4) {
        int s0 = g_csr[e], s1 = g_csr[e + 1], s2 = g_csr[e + 2], s3 = g_csr[e + 3];
        tacc += (g_dinv[s0] + g_dinv[s1]) + (g_dinv[s2] + g_dinv[s3]);
        if (lane < 20) {
            float4 v0 = h4cvt(S[(size_t)s0 * 20 + lane]);
            float4 v1 = h4cvt(S[(size_t)s1 * 20 + lane]);
            float4 v2 = h4cvt(S[(size_t)s2 * 20 + lane]);
            float4 v3 = h4cvt(S[(size_t)s3 * 20 + lane]);
            acc.x += (v0.x + v1.x) + (v2.x + v3.x);
            acc.y += (v0.y + v1.y) + (v2.y + v3.y);
            acc.z += (v0.z + v1.z) + (v2.z + v3.z);
            acc.w += (v0.w + v1.w) + (v2.w + v3.w);
        }
    }
    for (; e < end; e++) {
        int s0 = g_csr[e];
        tacc += g_dinv[s0];
        if (lane < 20) {
            float4 v0 = h4cvt(S[(size_t)s0 * 20 + lane]);
            acc.x += v0.x; acc.y += v0.y; acc.z += v0.z; acc.w += v0.w;
        }
    }
    if (lane < 20) {
        acc.x *= di; acc.y *= di; acc.z *= di; acc.w *= di;
        ((uint2*)dst)[(size_t)gw * 20 + lane] = h4pack(acc);
    }
    if (lane == 0) g_t[gw] = tacc;
}

// ---------------- gather2: fp16 src, 128 dims; fp16 dst; no dinv loads ----------------
__global__ void __launch_bounds__(256) k_gather2(const __half* __restrict__ src,
                                                 __half* __restrict__ dst) {
    int gw = (blockIdx.x * 256 + threadIdx.x) >> 5;
    if (gw >= NN) return;
    int lane = threadIdx.x & 31;
    float di = g_dinv[gw];
    int beg = g_off[gw], end = g_off[gw + 1];
    const uint2* S = (const uint2*)src;   // 32 uint2 per row
    float4 acc = h4cvt(S[(size_t)gw * 32 + lane]);
    int e = beg;
    for (; e + 3 < end; e += 4) {
        int s0 = g_csr[e], s1 = g_csr[e + 1], s2 = g_csr[e + 2], s3 = g_csr[e + 3];
        float4 v0 = h4cvt(S[(size_t)s0 * 32 + lane]);
        float4 v1 = h4cvt(S[(size_t)s1 * 32 + lane]);
        float4 v2 = h4cvt(S[(size_t)s2 * 32 + lane]);
        float4 v3 = h4cvt(S[(size_t)s3 * 32 + lane]);
        acc.x += (v0.x + v1.x) + (v2.x + v3.x);
        acc.y += (v0.y + v1.y) + (v2.y + v3.y);
        acc.z += (v0.z + v1.z) + (v2.z + v3.z);
        acc.w += (v0.w + v1.w) + (v2.w + v3.w);
    }
    for (; e < end; e++) {
        int s0 = g_csr[e];
        float4 v0 = h4cvt(S[(size_t)s0 * 32 + lane]);
        acc.x += v0.x; acc.y += v0.y; acc.z += v0.z; acc.w += v0.w;
    }
    acc.x *= di; acc.y *= di; acc.z *= di; acc.w *= di;
    ((uint2*)dst)[(size_t)gw * 32 + lane] = h4pack(acc);
}

// ---------------- fp16 m16n8k16 mma GEMM, cp.async double buffered ----------------
// A: fp16 [M][KH] row-major. B: fp16 [128 n][KH] (pre-transposed).
// EPI 0: relu(+bias), store fp16 (v * dinv_row) to C16, fused BN stats -> statp
// EPI 1: v = acc + bias + (dinv*t)*cvec; u = relu(v); NO gmem matrix write.
//        Fused pool via smem staging + per-graph-segment atomics; BN2 stats -> statp.
template <int KH, int KTILES, int EPI>
__global__ void __launch_bounds__(256) gemm_h(const __half* __restrict__ A,
                                              const __half* __restrict__ B,
                                              const float* __restrict__ bias,
                                              const float* __restrict__ cvec,
                                              float* __restrict__ statp,
                                              __half* __restrict__ C16,
                                              const int* __restrict__ ib, int M) {
    extern __shared__ float Udyn[];     // EPI1 only: [128][129] staged relu(out2)
    __shared__ __half As[2][128][24];   // stride 24 halves = 48B (conflict-free frags)
    __shared__ __half Bs[2][128][24];
    __shared__ float sS[4][128];
    __shared__ float sQ[4][128];
    __shared__ int   sib[128];
    int tid = threadIdx.x, lane = tid & 31, wid = tid >> 5;
    int gid = lane >> 2, tig = lane & 3;
    int wm = wid & 3, wn = wid >> 2;
    int rbase = wm * 32, cbase = wn * 64;
    int row0 = blockIdx.x << 7;

    float cacc[2][8][4];
#pragma unroll
    for (int mi = 0; mi < 2; mi++)
#pragma unroll
        for (int ni = 0; ni < 8; ni++)
#pragma unroll
            for (int q = 0; q < 4; q++) cacc[mi][ni][q] = 0.f;

    int arow = tid >> 1, aseg = tid & 1;   // A: row, 16B segment (8 halves)
    uint32_t aaddr[2], baddr[2];
#pragma unroll
    for (int b = 0; b < 2; b++) {
        aaddr[b] = (uint32_t)__cvta_generic_to_shared(&As[b][arow][aseg * 8]);
        baddr[b] = (uint32_t)__cvta_generic_to_shared(&Bs[b][arow][aseg * 8]);
    }

    auto load_chunk = [&](int kc, int buf) {
        int grow = row0 + arow;
        const __half* asrc = A + ((grow < M ? (size_t)grow : 0) * KH + kc * 16 + aseg * 8);
        CP_A16(aaddr[buf], asrc, (grow < M) ? 16u : 0u);
        const __half* bsrc = B + ((size_t)arow * KH + kc * 16 + aseg * 8);
        CP_A16(baddr[buf], bsrc, 16u);
    };

    load_chunk(0, 0);
    CP_COMMIT();

    for (int kc = 0; kc < KTILES; kc++) {
        if (kc + 1 < KTILES) {
            load_chunk(kc + 1, (kc + 1) & 1);
            CP_COMMIT();
            asm volatile("cp.async.wait_group 1;" ::: "memory");
        } else {
            asm volatile("cp.async.wait_group 0;" ::: "memory");
        }
        __syncthreads();
        int buf = kc & 1;
        uint32_t af[2][4];
#pragma unroll
        for (int mi = 0; mi < 2; mi++) {
            int rr = rbase + mi * 16 + gid;
            af[mi][0] = *(const uint32_t*)&As[buf][rr][tig * 2];
            af[mi][1] = *(const uint32_t*)&As[buf][rr + 8][tig * 2];
            af[mi][2] = *(const uint32_t*)&As[buf][rr][tig * 2 + 8];
            af[mi][3] = *(const uint32_t*)&As[buf][rr + 8][tig * 2 + 8];
        }
        uint32_t bf[8][2];
#pragma unroll
        for (int ni = 0; ni < 8; ni++) {
            int nn = cbase + ni * 8 + gid;
            bf[ni][0] = *(const uint32_t*)&Bs[buf][nn][tig * 2];
            bf[ni][1] = *(const uint32_t*)&Bs[buf][nn][tig * 2 + 8];
        }
#pragma unroll
        for (int mi = 0; mi < 2; mi++)
#pragma unroll
            for (int ni = 0; ni < 8; ni++) {
                asm volatile(
                    "mma.sync.aligned.m16n8k16.row.col.f32.f16.f16.f32 "
                    "{%0,%1,%2,%3}, {%4,%5,%6,%7}, {%8,%9}, {%0,%1,%2,%3};"
                    : "+f"(cacc[mi][ni][0]), "+f"(cacc[mi][ni][1]),
                      "+f"(cacc[mi][ni][2]), "+f"(cacc[mi][ni][3])
                    : "r"(af[mi][0]), "r"(af[mi][1]), "r"(af[mi][2]), "r"(af[mi][3]),
                      "r"(bf[ni][0]), "r"(bf[ni][1]));
            }
        __syncthreads();
    }

    float bs[8][2], cvv[8][2];
#pragma unroll
    for (int ni = 0; ni < 8; ni++) {
        int col = cbase + ni * 8 + tig * 2;
        bs[ni][0] = bias[col];
        bs[ni][1] = bias[col + 1];
        if (EPI == 1) { cvv[ni][0] = cvec[col]; cvv[ni][1] = cvec[col + 1]; }
    }

    if (EPI == 0) {
        float sacc[8][2], qacc[8][2];
#pragma unroll
        for (int ni = 0; ni < 8; ni++) {
            sacc[ni][0] = 0.f; sacc[ni][1] = 0.f;
            qacc[ni][0] = 0.f; qacc[ni][1] = 0.f;
        }
#pragma unroll
        for (int mi = 0; mi < 2; mi++) {
            int rA = row0 + rbase + mi * 16 + gid;
            int rB = rA + 8;
            float dA = (rA < M) ? g_dinv[rA] : 0.f;
            float dB = (rB < M) ? g_dinv[rB] : 0.f;
#pragma unroll
            for (int ni = 0; ni < 8; ni++) {
                int col = cbase + ni * 8 + tig * 2;
                float v0 = fmaxf(cacc[mi][ni][0] + bs[ni][0], 0.f);
                float v1 = fmaxf(cacc[mi][ni][1] + bs[ni][1], 0.f);
                float v2 = fmaxf(cacc[mi][ni][2] + bs[ni][0], 0.f);
                float v3 = fmaxf(cacc[mi][ni][3] + bs[ni][1], 0.f);
                if (rA < M) {
                    sacc[ni][0] += v0; qacc[ni][0] += v0 * v0;
                    sacc[ni][1] += v1; qacc[ni][1] += v1 * v1;
                    ((__half2*)C16)[(size_t)rA * 64 + (col >> 1)] =
                        __floats2half2_rn(v0 * dA, v1 * dA);
                }
                if (rB < M) {
                    sacc[ni][0] += v2; qacc[ni][0] += v2 * v2;
                    sacc[ni][1] += v3; qacc[ni][1] += v3 * v3;
                    ((__half2*)C16)[(size_t)rB * 64 + (col >> 1)] =
                        __floats2half2_rn(v2 * dB, v3 * dB);
                }
            }
        }
#pragma unroll
        for (int ni = 0; ni < 8; ni++)
#pragma unroll
            for (int j = 0; j < 2; j++) {
#pragma unroll
                for (int off = 4; off < 32; off <<= 1) {
                    sacc[ni][j] += __shfl_xor_sync(0xffffffffu, sacc[ni][j], off);
                    qacc[ni][j] += __shfl_xor_sync(0xffffffffu, qacc[ni][j], off);
                }
            }
        if (gid == 0) {
#pragma unroll
            for (int ni = 0; ni < 8; ni++) {
                int col = cbase + ni * 8 + tig * 2;
                sS[wm][col] = sacc[ni][0]; sS[wm][col + 1] = sacc[ni][1];
                sQ[wm][col] = qacc[ni][0]; sQ[wm][col + 1] = qacc[ni][1];
            }
        }
        __syncthreads();
        if (tid < 128) {
            float s = 0.f, q = 0.f;
#pragma unroll
            for (int w = 0; w < 4; w++) { s += sS[w][tid]; q += sQ[w][tid]; }
            atomicAdd(&statp[tid], s);
            atomicAdd(&statp[128 + tid], q);
        }
    } else {
        // EPI 1: stage relu(out2) to smem, then per-graph pooled reduction
#pragma unroll
        for (int mi = 0; mi < 2; mi++) {
            int lrA = rbase + mi * 16 + gid;
            int rA = row0 + lrA, rB = rA + 8;
            float sA = (rA < M) ? g_dinv[rA] * g_t[rA] : 0.f;
            float sB = (rB < M) ? g_dinv[rB] * g_t[rB] : 0.f;
#pragma unroll
            for (int ni = 0; ni < 8; ni++) {
                int col = cbase + ni * 8 + tig * 2;
                float v0 = fmaxf(cacc[mi][ni][0] + bs[ni][0] + sA * cvv[ni][0], 0.f);
                float v1 = fmaxf(cacc[mi][ni][1] + bs[ni][1] + sA * cvv[ni][1], 0.f);
                float v2 = fmaxf(cacc[mi][ni][2] + bs[ni][0] + sB * cvv[ni][0], 0.f);
                float v3 = fmaxf(cacc[mi][ni][3] + bs[ni][1] + sB * cvv[ni][1], 0.f);
                Udyn[lrA * 129 + col] = v0;
                Udyn[lrA * 129 + col + 1] = v1;
                Udyn[(lrA + 8) * 129 + col] = v2;
                Udyn[(lrA + 8) * 129 + col + 1] = v3;
            }
        }
        if (tid < 128) {
            int grow = row0 + tid;
            sib[tid] = (grow < M) ? ib[grow] : -1;
        }
        __syncthreads();
        int col = tid & 127, half = tid >> 7;
        int r0 = half * 64, r1 = r0 + 64;
        float s = 0.f, q = 0.f, mx = 0.f, mn = 0.f;
        int gcur = -1;
        for (int r = r0; r < r1; r++) {
            int g = sib[r];
            if (g < 0) break;
            float u = Udyn[r * 129 + col];
            s += u; q += u * u;
            if (g != gcur) {
                if (gcur >= 0) {
                    atomicMax((int*)&g_smax[gcur * HF + col], __float_as_int(mx));
                    atomicMin((int*)&g_smin[gcur * HF + col], __float_as_int(mn));
                }
                gcur = g; mx = u; mn = u;
            } else {
                mx = fmaxf(mx, u); mn = fminf(mn, u);
            }
        }
        if (gcur >= 0) {
            atomicMax((int*)&g_smax[gcur * HF + col], __float_as_int(mx));
            atomicMin((int*)&g_smin[gcur * HF + col], __float_as_int(mn));
        }
        atomicAdd(&statp[col], s);
        atomicAdd(&statp[HF + col], q);
    }
}

// ---------------- FFMA2 GEMM (cell branch only) ----------------
template <int EPI, bool ALIGN4>
__global__ void __launch_bounds__(256, 2) gemm_t(const float* __restrict__ A,
                                                 const float* __restrict__ B,
                                                 const float* __restrict__ bias,
                                                 float* __restrict__ C,
                                                 float* __restrict__ statp,
                                                 int M, int K) {
    __shared__ float As[16][132];
    __shared__ float Bs[16][128];
    __shared__ float redS[16][128];
    __shared__ float redQ[16][128];
    int tid = threadIdx.x;
    int tx = tid & 15;
    int ty = tid >> 4;
    int row0 = blockIdx.x * 128;

    unsigned long long acc[8][4];
#pragma unroll
    for (int r = 0; r < 8; r++)
#pragma unroll
        for (int c = 0; c < 4; c++) acc[r][c] = 0ULL;

    for (int k0 = 0; k0 < K; k0 += 16) {
#pragma unroll
        for (int s = tid; s < 512; s += 256) {
            int r = s >> 2, kq = s & 3;
            int grow = row0 + r, gk = k0 + kq * 4;
            float4 v = make_float4(0.f, 0.f, 0.f, 0.f);
            if (grow < M) {
                const float* arow = A + (size_t)grow * K;
                if (gk + 3 < K) {
                    if (ALIGN4) {
                        v = *(const float4*)&arow[gk];
                    } else {
                        float2 v0 = *(const float2*)&arow[gk];
                        float2 v1 = *(const float2*)&arow[gk + 2];
                        v = make_float4(v0.x, v0.y, v1.x, v1.y);
                    }
                } else {
                    if (gk + 0 < K) v.x = arow[gk + 0];
                    if (gk + 1 < K) v.y = arow[gk + 1];
                    if (gk + 2 < K) v.z = arow[gk + 2];
                    if (gk + 3 < K) v.w = arow[gk + 3];
                }
            }
            As[kq * 4 + 0][r] = v.x;
            As[kq * 4 + 1][r] = v.y;
            As[kq * 4 + 2][r] = v.z;
            As[kq * 4 + 3][r] = v.w;
        }
#pragma unroll
        for (int s = tid; s < 512; s += 256) {
            int kk = s >> 5, nq = s & 31;
            int gk = k0 + kk;
            float4 v = make_float4(0.f, 0.f, 0.f, 0.f);
            if (gk < K) v = *(const float4*)&B[(size_t)gk * 128 + nq * 4];
            *(float4*)&Bs[kk][nq * 4] = v;
        }
        __syncthreads();
#pragma unroll
        for (int kk = 0; kk < 16; kk++) {
            float4 a0 = *(const float4*)&As[kk][ty * 8];
            float4 a1 = *(const float4*)&As[kk][ty * 8 + 4];
            ulonglong2 bA = *(const ulonglong2*)&Bs[kk][tx * 8];
            ulonglong2 bB = *(const ulonglong2*)&Bs[kk][tx * 8 + 4];
            unsigned long long bv[4] = {bA.x, bA.y, bB.x, bB.y};
            float av[8] = {a0.x, a0.y, a0.z, a0.w, a1.x, a1.y, a1.z, a1.w};
#pragma unroll
            for (int r = 0; r < 8; r++) {
                unsigned long long ap;
                unsigned int ai = __float_as_uint(av[r]);
                asm("mov.b64 %0, {%1, %1};" : "=l"(ap) : "r"(ai));
#pragma unroll
                for (int c = 0; c < 4; c++) {
                    asm("fma.rn.f32x2 %0, %1, %2, %3;"
                        : "=l"(acc[r][c]) : "l"(ap), "l"(bv[c]), "l"(acc[r][c]));
                }
            }
        }
        __syncthreads();
    }

    float bv0[8];
#pragma unroll
    for (int c = 0; c < 8; c++) bv0[c] = bias[tx * 8 + c];
    float s8[8], q8[8];
    if (EPI == 2) {
#pragma unroll
        for (int c = 0; c < 8; c++) { s8[c] = 0.f; q8[c] = 0.f; }
    }
#pragma unroll
    for (int r = 0; r < 8; r++) {
        int grow = row0 + ty * 8 + r;
        if (grow < M) {
            float o[8];
#pragma unroll
            for (int c = 0; c < 4; c++) {
                float lo, hi;
                asm("mov.b64 {%0, %1}, %2;" : "=f"(lo), "=f"(hi) : "l"(acc[r][c]));
                o[2 * c] = lo; o[2 * c + 1] = hi;
            }
#pragma unroll
            for (int c = 0; c < 8; c++) {
                float v = o[c] + bv0[c];
                if (EPI == 2) v = tanhf(v);
                if (EPI == 3) v = fmaxf(v, 0.f);
                if (EPI == 2) { s8[c] += v; q8[c] += v * v; }
                o[c] = v;
            }
            *(float4*)&C[(size_t)grow * 128 + tx * 8] = make_float4(o[0], o[1], o[2], o[3]);
            *(float4*)&C[(size_t)grow * 128 + tx * 8 + 4] = make_float4(o[4], o[5], o[6], o[7]);
        }
    }
    if (EPI == 2) {
#pragma unroll
        for (int c = 0; c < 8; c++) { redS[ty][tx * 8 + c] = s8[c]; redQ[ty][tx * 8 + c] = q8[c]; }
        __syncthreads();
        if (tid < 128) {
            float s = 0.f, q = 0.f;
#pragma unroll
            for (int t = 0; t < 16; t++) { s += redS[t][tid]; q += redQ[t][tid]; }
            atomicAdd(&statp[tid], s);
            atomicAdd(&statp[128 + tid], q);
        }
    }
}

// ---------------- parallel fold BN1 into W2 ([n][k] fp16 out) ----------------
__global__ void __launch_bounds__(128) k_fold1p(const float* __restrict__ g1,
                                                const float* __restrict__ be1,
                                                const float* __restrict__ W2) {
    __shared__ float red[128];
    int n = blockIdx.x;
    int k = threadIdx.x;
    float mu = g_stat1[k] * (1.0f / NN);
    float var = g_stat1[HF + k] * (1.0f / NN) - mu * mu;
    float sck = g1[k] * rsqrtf(var + BN_EPS);
    float shk = be1[k] - mu * sck;
    float w = W2[k * HF + n];
    g_W2h[n * HF + k] = __float2half_rn(sck * w);
    red[k] = shk * w;
    __syncthreads();
    for (int o = 64; o > 0; o >>= 1) {
        if (k < o) red[k] += red[k + o];
        __syncthreads();
    }
    if (k == 0) g_c2[n] = red[0];
}

// ---------------- fold cell BN into Wc2 (zeroes g_statc) ----------------
__global__ void k_foldc(const float* __restrict__ gc1, const float* __restrict__ bec1,
                        const float* __restrict__ Wc2, const float* __restrict__ bc2) {
    __shared__ float sc[HF], sh[HF];
    int n = threadIdx.x;
    float mu = g_statc[n] * (1.0f / NG);
    float var = g_statc[HF + n] * (1.0f / NG) - mu * mu;
    g_statc[n] = 0.f; g_statc[HF + n] = 0.f;
    float s = gc1[n] * rsqrtf(var + BN_EPS);
    sc[n] = s;
    sh[n] = bec1[n] - mu * s;
    __syncthreads();
    float c = 0.f;
#pragma unroll 8
    for (int k = 0; k < HF; k++) {
        float w = Wc2[k * HF + n];
        g_Wc2p[k * HF + n] = sc[k] * w;
        c += sh[k] * w;
    }
    g_bc2p[n] = bc2[n] + c;
}

// ---------------- final select with BN2 scale computed inline ----------------
__global__ void k_final(const float* __restrict__ g2, const float* __restrict__ be2,
                        float* __restrict__ out) {
    int idx = blockIdx.x * blockDim.x + threadIdx.x;
    if (idx < 2 * HF) g_stat1[idx] = 0.f;
    if (idx >= NG * HF) return;
    int k = idx & 127;
    float mu = g_stat2[k] * (1.0f / NN);
    float var = g_stat2[HF + k] * (1.0f / NN) - mu * mu;
    float s = g2[k] * rsqrtf(var + BN_EPS);
    float sh = be2[k] - mu * s;
    float mx = g_smax[idx];
    float r;
    if (mx == neg_inf()) {
        r = neg_inf();
    } else {
        float v = (s >= 0.f) ? mx : g_smin[idx];
        r = s * v + sh;
    }
    out[idx] = r;
}

// ---------------- host ----------------
extern "C" void kernel_launch(void* const* d_in, const int* in_sizes, int n_in,
                              void* d_out, int out_size) {
    const float* drug = (const float*)d_in[0];
    const int* ei = (const int*)d_in[1];
    const int* ib = (const int*)d_in[2];
    const float* gexpr = (const float*)d_in[3];
    const float* W1 = (const float*)d_in[4];
    const float* b1 = (const float*)d_in[5];
    const float* g1 = (const float*)d_in[6];
    const float* be1 = (const float*)d_in[7];
    const float* W2 = (const float*)d_in[8];
    const float* b2 = (const float*)d_in[9];
    const float* g2 = (const float*)d_in[10];
    const float* be2 = (const float*)d_in[11];
    const float* Wc1 = (const float*)d_in[12];
    const float* bc1 = (const float*)d_in[13];
    const float* gc1 = (const float*)d_in[14];
    const float* bec1 = (const float*)d_in[15];
    const float* Wc2 = (const float*)d_in[16];
    const float* bc2 = (const float*)d_in[17];
    float* out = (float*)d_out;

    float *cellp, *stat1p, *stat2p, *statcp, *c2p, *Wc2pp, *bc2pp;
    __half *x16p, *dp16p, *h16p, *y16p, *W1hp, *W2hp;
    cudaGetSymbolAddress((void**)&dp16p, g_dp16);
    cudaGetSymbolAddress((void**)&h16p, g_h16);
    cudaGetSymbolAddress((void**)&x16p, g_x16);
    cudaGetSymbolAddress((void**)&y16p, g_y16);
    cudaGetSymbolAddress((void**)&W1hp, g_W1h);
    cudaGetSymbolAddress((void**)&W2hp, g_W2h);
    cudaGetSymbolAddress((void**)&cellp, g_cell);
    cudaGetSymbolAddress((void**)&stat1p, g_stat1);
    cudaGetSymbolAddress((void**)&stat2p, g_stat2);
    cudaGetSymbolAddress((void**)&statcp, g_statc);
    cudaGetSymbolAddress((void**)&c2p, g_c2);
    cudaGetSymbolAddress((void**)&Wc2pp, g_Wc2p);
    cudaGetSymbolAddress((void**)&bc2pp, g_bc2p);

    const int USMEM = 128 * 129 * 4;
    cudaFuncSetAttribute(gemm_h<HF, 8, 1>, cudaFuncAttributeMaxDynamicSharedMemorySize, USMEM);

    static cudaStream_t sB = nullptr, sC = nullptr;
    static cudaEvent_t eStart = nullptr, e0 = nullptr, eB = nullptr, eC = nullptr,
                       eF = nullptr, eGB = nullptr, eG1 = nullptr;
    if (!sB) {
        cudaStreamCreateWithFlags(&sB, cudaStreamNonBlocking);
        cudaStreamCreateWithFlags(&sC, cudaStreamNonBlocking);
        cudaEventCreateWithFlags(&eStart, cudaEventDisableTiming);
        cudaEventCreateWithFlags(&e0, cudaEventDisableTiming);
        cudaEventCreateWithFlags(&eB, cudaEventDisableTiming);
        cudaEventCreateWithFlags(&eC, cudaEventDisableTiming);
        cudaEventCreateWithFlags(&eF, cudaEventDisableTiming);
        cudaEventCreateWithFlags(&eGB, cudaEventDisableTiming);
        cudaEventCreateWithFlags(&eG1, cudaEventDisableTiming);
    }

    // origin stream: fork anchor
    k_nop<<<1, 32>>>();
    cudaEventRecord(eStart, 0);

    // branch C (forked): pool-accumulator init (+stat2 zero) + cell branch
    cudaStreamWaitEvent(sC, eStart, 0);
    k_ginit<<<(NG * HF + 255) / 256, 256, 0, sC>>>();
    cudaEventRecord(eGB, sC);
    gemm_t<2, false><<<(NG + 127) / 128, 256, 0, sC>>>(gexpr, Wc1, bc1, cellp, statcp, NG, KCELL);
    k_foldc<<<1, HF, 0, sC>>>(gc1, bec1, Wc2, bc2);
    gemm_t<3, true><<<(NG + 127) / 128, 256, 0, sC>>>(cellp, Wc2pp, bc2pp, out + NG * HF, nullptr, NG, HF);
    cudaEventRecord(eC, sC);

    // origin: indegree count
    k_cnt<<<(NE + 255) / 256, 256>>>(ei);
    cudaEventRecord(e0, 0);

    // branch B: CSR build
    cudaStreamWaitEvent(sB, e0, 0);
    k_scan1<<<SCAN_NB, 256, 0, sB>>>();
    k_scan3<<<(NN + 255) / 256, 256, 0, sB>>>();
    k_fill<<<(NE + 255) / 256, 256, 0, sB>>>(ei);
    cudaEventRecord(eB, sB);

    // origin: dinv + fp16 pre-scaled drug padding + fp16 transposed W1
    k_pad<<<(NN * 40 + 255) / 256, 256>>>(drug);
    k_padW<<<(HF * KPAD + 255) / 256, 256>>>(W1);

    // join CSR; layer 1: gather (fp16) -> fp16 mma gemm1 (relu + bias + stats, fp16*dinv out)
    cudaStreamWaitEvent(0, eB, 0);
    k_gather1<<<(NN * 32 + 255) / 256, 256>>>(dp16p, h16p);
    gemm_h<KPAD, 5, 0><<<(NN + 127) / 128, 256>>>(h16p, W1hp, b1, nullptr, stat1p, x16p, nullptr, NN);
    cudaEventRecord(eG1, 0);

    // stream B: parallel fold1 concurrent with gather2
    cudaStreamWaitEvent(sB, eG1, 0);
    k_fold1p<<<HF, HF, 0, sB>>>(g1, be1, W2);
    cudaEventRecord(eF, sB);

    // layer 2: gather fp16 -> join fold + pool-init -> fp16 mma gemm2 (pool fused)
    k_gather2<<<(NN * 32 + 255) / 256, 256>>>(x16p, y16p);
    cudaStreamWaitEvent(0, eF, 0);
    cudaStreamWaitEvent(0, eGB, 0);
    gemm_h<HF, 8, 1><<<(NN + 127) / 128, 256, USMEM>>>(y16p, W2hp, b2, c2p, stat2p, nullptr, ib, NN);

    // final select (BN2 fold inline)
    k_final<<<(NG * HF + 255) / 256, 256>>>(g2, be2, out);

    cudaStreamWaitEvent(0, eC, 0);
}